// round 1
// baseline (speedup 1.0000x reference)
#include <cuda_runtime.h>
#include <math.h>

#define NB   2
#define TT   4096
#define HIDD 1024
#define NHH  16
#define DD   64
#define TOPKK 16
#define NEGV (-10000.0f)
#define WK   289   /* 3*96 local window + 1 global token */

// ---------------- device scratch (allocation-free rule: device globals) ----------
__device__ float g_q[(size_t)NB*NHH*TT*DD];
__device__ float g_k[(size_t)NB*NHH*TT*DD];
__device__ float g_v[(size_t)NB*NHH*TT*DD];
__device__ float g_ctxg[(size_t)NB*NHH*TT*DD];
__device__ float g_lseg[(size_t)NB*NHH*TT];
__device__ int   g_gidx[(size_t)NB*NHH*(TT/4)];
__device__ int   g_lidx[(size_t)NB*NHH*(3*TT/4)];

// ---------------- fp32 tiled GEMM: out[n,h,t,d] = X @ W^T + b ---------------------
// X: (NB*TT, HIDD) row-major. W: (HIDD, HIDD) row-major (we need X @ W^T).
// 128x128 block tile, BK=8, 256 threads, 8x8 per-thread micro tile.
__global__ void gemm_proj_kernel(const float* __restrict__ A,
                                 const float* __restrict__ W,
                                 const float* __restrict__ bias,
                                 float* __restrict__ out)
{
    __shared__ float As[8][128];
    __shared__ float Bs[8][128];
    const int tid = threadIdx.x;
    const int m0 = blockIdx.y * 128;
    const int n0 = blockIdx.x * 128;
    const int ty = tid >> 4;        // 0..15
    const int tx = tid & 15;        // 0..15
    const int lr = tid >> 1;        // 0..127
    const int lc = (tid & 1) * 4;   // 0 or 4

    const float* Ap = A + (size_t)(m0 + lr) * HIDD + lc;
    const float* Wp = W + (size_t)(n0 + lr) * HIDD + lc;

    float acc[8][8];
#pragma unroll
    for (int i = 0; i < 8; i++)
#pragma unroll
        for (int j = 0; j < 8; j++) acc[i][j] = 0.0f;

    for (int kt = 0; kt < HIDD; kt += 8) {
        float4 a4 = *(const float4*)(Ap + kt);
        float4 b4 = *(const float4*)(Wp + kt);
        As[lc + 0][lr] = a4.x; As[lc + 1][lr] = a4.y;
        As[lc + 2][lr] = a4.z; As[lc + 3][lr] = a4.w;
        Bs[lc + 0][lr] = b4.x; Bs[lc + 1][lr] = b4.y;
        Bs[lc + 2][lr] = b4.z; Bs[lc + 3][lr] = b4.w;
        __syncthreads();
#pragma unroll
        for (int k = 0; k < 8; k++) {
            float a[8], b[8];
#pragma unroll
            for (int i = 0; i < 8; i++) a[i] = As[k][ty * 8 + i];
#pragma unroll
            for (int j = 0; j < 8; j++) b[j] = Bs[k][tx * 8 + j];
#pragma unroll
            for (int i = 0; i < 8; i++)
#pragma unroll
                for (int j = 0; j < 8; j++)
                    acc[i][j] = fmaf(a[i], b[j], acc[i][j]);
        }
        __syncthreads();
    }

    // epilogue: remap flat (m, col) -> (n, h, t, d) layout, add bias
#pragma unroll
    for (int i = 0; i < 8; i++) {
        int row = m0 + ty * 8 + i;
        int nb  = row >> 12;        // row / 4096
        int t   = row & (TT - 1);
#pragma unroll
        for (int j = 0; j < 8; j++) {
            int col = n0 + tx * 8 + j;
            int h = col >> 6;
            int d = col & 63;
            out[(((size_t)(nb * NHH + h)) * TT + t) * DD + d] = acc[i][j] + bias[col];
        }
    }
}

// ---------------- norm-based top-k selection per 64-token block -------------------
__global__ void select_kernel(const float* __restrict__ mask,
                              const float* __restrict__ bq)
{
    const int blk = blockIdx.x;   // 0..63
    const int h   = blockIdx.y;
    const int n   = blockIdx.z;
    const int i   = threadIdx.x;  // 0..63
    __shared__ float norms[64];
    __shared__ int flags[64];

    const int token = blk * 64 + i;
    const float* kr = g_k + (((size_t)(n * NHH + h)) * TT + token) * DD;
    const float* bqr = bq + h * DD;
    float s = 0.0f;
#pragma unroll
    for (int d = 0; d < DD; d++) { float vv = kr[d] + bqr[d]; s += vv * vv; }
    if (mask[n * TT + token] != 0.0f) s = 0.0f;   // valid = (mask == 0)
    norms[i] = s;
    __syncthreads();

    // stable ascending argsort rank
    float mine = norms[i];
    int rank = 0;
    for (int j = 0; j < 64; j++) {
        float nj = norms[j];
        rank += (nj < mine) || (nj == mine && j < i);
    }
    int top = (rank >= 64 - TOPKK) ? 1 : 0;
    flags[i] = top;
    __syncthreads();

    int pos = 0;
    for (int j = 0; j < i; j++) pos += flags[j];
    if (top)
        g_gidx[((size_t)(n * NHH + h)) * (TT / 4) + blk * TOPKK + pos] = token;
    else
        g_lidx[((size_t)(n * NHH + h)) * (3 * TT / 4) + blk * 48 + (i - pos)] = token;
}

// ---------------- global pass: 64 queries x 48 gathered keys ----------------------
__global__ void attn_global_kernel(const float* __restrict__ mask)
{
    const int qb = blockIdx.x;    // 0..63
    const int h  = blockIdx.y;
    const int n  = blockIdx.z;
    const int tid = threadIdx.x;  // 64 threads
    __shared__ float ks[48 * 64];
    __shared__ float vs[48 * 64];
    __shared__ float ms[48];
    __shared__ float sc[64 * 49]; // padded stride 49

    const size_t ho = (size_t)(n * NHH + h);
    const float* kb = g_k + ho * TT * DD;
    const float* vb = g_v + ho * TT * DD;
    const int* gix = g_gidx + ho * (TT / 4);

    for (int idx = tid; idx < 48 * 64; idx += 64) {
        int r = idx >> 6, c = idx & 63;
        int g = qb * 16 - 16 + r;
        float kvv = 0.0f, vvv = 0.0f;
        if (g >= 0 && g < TT / 4) {
            int src = gix[g];
            kvv = kb[(size_t)src * DD + c];
            vvv = vb[(size_t)src * DD + c];
            if (c == 0) ms[r] = mask[n * TT + src];
        } else {
            if (c == 0) ms[r] = NEGV;
        }
        ks[idx] = kvv; vs[idx] = vvv;
    }
    __syncthreads();

    const int qi = tid;
    const int tq = qb * 64 + qi;
    const float* qr = g_q + (ho * TT + tq) * DD;
    float qreg[64];
#pragma unroll
    for (int d = 0; d < 64; d++) qreg[d] = qr[d];

    float* row = sc + qi * 49;
    float mmax = -1e30f;
    for (int kk = 0; kk < 48; kk++) {
        float dot = 0.0f;
#pragma unroll
        for (int d = 0; d < 64; d++) dot = fmaf(qreg[d], ks[kk * 64 + d], dot);
        float s = dot * 0.125f + ms[kk];
        row[kk] = s;
        mmax = fmaxf(mmax, s);
    }
    float l = 0.0f;
    for (int kk = 0; kk < 48; kk++) {
        float p = __expf(row[kk] - mmax);
        row[kk] = p;
        l += p;
    }
    g_lseg[ho * TT + tq] = mmax + logf(l);
    float inv = 1.0f / l;
    float* ctxr = g_ctxg + (ho * TT + tq) * DD;
    for (int d0 = 0; d0 < 64; d0 += 32) {
        float acc[32];
#pragma unroll
        for (int dd = 0; dd < 32; dd++) acc[dd] = 0.0f;
        for (int kk = 0; kk < 48; kk++) {
            float w = row[kk];
#pragma unroll
            for (int dd = 0; dd < 32; dd++)
                acc[dd] = fmaf(w, vs[kk * 64 + d0 + dd], acc[dd]);
        }
#pragma unroll
        for (int dd = 0; dd < 32; dd++) ctxr[d0 + dd] = acc[dd] * inv;
    }
}

// ---------------- local pass (flash, 2 threads/query) + merge + output ------------
__global__ void attn_local_kernel(const float* __restrict__ mask,
                                  float* __restrict__ out)
{
    extern __shared__ float sm[];
    float* ks = sm;                // WK*64
    float* vs = sm + WK * 64;      // WK*64
    float* ms = sm + 2 * WK * 64;  // WK

    const int qb = blockIdx.x;     // 0..31
    const int h  = blockIdx.y;
    const int n  = blockIdx.z;
    const int tid = threadIdx.x;   // 256

    const size_t ho = (size_t)(n * NHH + h);
    const float* kb = g_k + ho * TT * DD;
    const float* vb = g_v + ho * TT * DD;
    const int* lix = g_lidx + ho * (3 * TT / 4);

    for (int idx = tid; idx < WK * 64; idx += 256) {
        int r = idx >> 6, c = idx & 63;
        float kvv, vvv;
        if (r == 288) {            // appended global token (k[...,0,:], mask 0)
            kvv = kb[c]; vvv = vb[c];
            if (c == 0) ms[r] = 0.0f;
        } else {
            int g = qb * 96 - 96 + r;
            if (g >= 0 && g < 3 * TT / 4) {
                int src = lix[g];
                kvv = kb[(size_t)src * DD + c];
                vvv = vb[(size_t)src * DD + c];
                if (c == 0) ms[r] = mask[n * TT + src];
            } else {
                kvv = 0.0f; vvv = 0.0f;
                if (c == 0) ms[r] = NEGV;
            }
        }
        ks[idx] = kvv; vs[idx] = vvv;
    }
    __syncthreads();

    const int qi = tid >> 1;
    const int half = tid & 1;
    const int d0 = half * 32;
    const int tq = qb * 128 + qi;
    const float* qr = g_q + (ho * TT + tq) * DD + d0;
    float qreg[32];
#pragma unroll
    for (int dd = 0; dd < 32; dd++) qreg[dd] = qr[dd];

    float m = -1e30f, l = 0.0f;
    float ctx[32];
#pragma unroll
    for (int dd = 0; dd < 32; dd++) ctx[dd] = 0.0f;

    for (int kk = 0; kk < WK; kk++) {
        const float* krow = ks + kk * 64 + d0;
        float part = 0.0f;
#pragma unroll
        for (int dd = 0; dd < 32; dd++) part = fmaf(qreg[dd], krow[dd], part);
        float dot = part + __shfl_xor_sync(0xffffffffu, part, 1);
        float s = dot * 0.125f + ms[kk];
        float mn = fmaxf(m, s);
        float corr = __expf(m - mn);
        float p = __expf(s - mn);
        l = l * corr + p;
        const float* vrow = vs + kk * 64 + d0;
#pragma unroll
        for (int dd = 0; dd < 32; dd++)
            ctx[dd] = fmaf(ctx[dd], corr, p * vrow[dd]);
        m = mn;
    }

    float lse_l = m + logf(l);
    float lg = g_lseg[ho * TT + tq];
    float pm = 1.0f / (1.0f + __expf(lg - lse_l));
    float invl = 1.0f / l;
    const float* cg = g_ctxg + (ho * TT + tq) * DD + d0;
    float* op = out + ((size_t)n * TT + tq) * HIDD + h * DD + d0;
#pragma unroll
    for (int dd = 0; dd < 32; dd++) {
        float cl = ctx[dd] * invl;
        float cgv = cg[dd];
        op[dd] = cgv + pm * (cl - cgv);
    }
}

// ---------------- BOS row: full unscaled attention over all keys ------------------
__global__ void bos_kernel(const float* __restrict__ mask,
                           float* __restrict__ out)
{
    const int h = blockIdx.x;
    const int n = blockIdx.y;
    const int tid = threadIdx.x;   // 128
    __shared__ float sc[TT];
    __shared__ float qs[64];
    __shared__ float red[128];

    const size_t ho = (size_t)(n * NHH + h);
    const float* kb = g_k + ho * TT * DD;
    const float* vb = g_v + ho * TT * DD;
    if (tid < 64) qs[tid] = g_q[(ho * TT) * DD + tid];
    __syncthreads();

    float lmax = -1e30f;
    for (int t = tid; t < TT; t += 128) {
        const float* kr = kb + (size_t)t * DD;
        float dot = 0.0f;
#pragma unroll
        for (int d = 0; d < 64; d++) dot = fmaf(qs[d], kr[d], dot);
        float s = dot + mask[n * TT + t];   // NOTE: no 1/sqrt(d) scale for BOS
        sc[t] = s;
        lmax = fmaxf(lmax, s);
    }
    red[tid] = lmax;
    __syncthreads();
    for (int off = 64; off > 0; off >>= 1) {
        if (tid < off) red[tid] = fmaxf(red[tid], red[tid + off]);
        __syncthreads();
    }
    float mmax = red[0];
    float lsum = 0.0f;
    for (int t = tid; t < TT; t += 128) {
        float p = __expf(sc[t] - mmax);
        sc[t] = p;
        lsum += p;
    }
    __syncthreads();              // everyone has read red[0]
    red[tid] = lsum;
    __syncthreads();
    for (int off = 64; off > 0; off >>= 1) {
        if (tid < off) red[tid] += red[tid + off];
        __syncthreads();
    }
    float inv = 1.0f / red[0];
    if (tid < 64) {
        int d = tid;
        float acc = 0.0f;
        for (int t = 0; t < TT; t++)
            acc = fmaf(sc[t], vb[(size_t)t * DD + d], acc);
        out[((size_t)n * TT) * HIDD + h * DD + d] = acc * inv;
    }
}

// ---------------- launch ----------------------------------------------------------
extern "C" void kernel_launch(void* const* d_in, const int* in_sizes, int n_in,
                              void* d_out, int out_size)
{
    (void)in_sizes; (void)n_in; (void)out_size;
    const float* hs   = (const float*)d_in[0];
    const float* mask = (const float*)d_in[1];
    const float* Wq   = (const float*)d_in[2];
    const float* bq   = (const float*)d_in[3];
    const float* Wk   = (const float*)d_in[4];
    const float* bk   = (const float*)d_in[5];
    const float* Wv   = (const float*)d_in[6];
    const float* bv   = (const float*)d_in[7];
    float* out = (float*)d_out;

    float *qp, *kp, *vp;
    cudaGetSymbolAddress((void**)&qp, g_q);
    cudaGetSymbolAddress((void**)&kp, g_k);
    cudaGetSymbolAddress((void**)&vp, g_v);

    dim3 ggrid(HIDD / 128, (NB * TT) / 128);   // (8, 64)
    gemm_proj_kernel<<<ggrid, 256>>>(hs, Wq, bq, qp);
    gemm_proj_kernel<<<ggrid, 256>>>(hs, Wk, bk, kp);
    gemm_proj_kernel<<<ggrid, 256>>>(hs, Wv, bv, vp);

    select_kernel<<<dim3(TT / 64, NHH, NB), 64>>>(mask, bq);

    attn_global_kernel<<<dim3(TT / 64, NHH, NB), 64>>>(mask);

    size_t lsmem = (size_t)(2 * WK * 64 + WK) * sizeof(float);   // ~149 KB
    cudaFuncSetAttribute(attn_local_kernel,
                         cudaFuncAttributeMaxDynamicSharedMemorySize, (int)lsmem);
    attn_local_kernel<<<dim3(TT / 128, NHH, NB), 256, lsmem>>>(mask, out);

    bos_kernel<<<dim3(NHH, NB), 128>>>(mask, out);
}

// round 2
// speedup vs baseline: 1.2237x; 1.2237x over previous
#include <cuda_runtime.h>
#include <cuda_bf16.h>
#include <math.h>

#define NB   2
#define TT   4096
#define HIDD 1024
#define NHH  16
#define DD   64
#define TOPKK 16
#define NEGV (-10000.0f)
#define WK   289   /* 3*96 local window + 1 global token */

// ---------------- device scratch (allocation-free rule: device globals) ----------
__device__ float g_q[(size_t)NB*NHH*TT*DD];
__device__ float g_k[(size_t)NB*NHH*TT*DD];
__device__ float g_v[(size_t)NB*NHH*TT*DD];
__device__ float g_ctxg[(size_t)NB*NHH*TT*DD];
__device__ float g_lseg[(size_t)NB*NHH*TT];
__device__ int   g_gidx[(size_t)NB*NHH*(TT/4)];
__device__ int   g_lidx[(size_t)NB*NHH*(3*TT/4)];

// ================= split-bf16 tensor-core GEMM: out = X @ W^T + b ================
// X: (NB*TT, HIDD) row-major, W: (HIDD, HIDD) row-major (n x k). Both k-contiguous.
// fp32 = hi(bf16) + lo(bf16); D += hi*hi + hi*lo + lo*hi  (fp32 accum).
// Tile 128x128x32, 256 threads = 8 warps (4m x 2n), warp tile 32x64.

__device__ __forceinline__ void mma_bf16(float& d0, float& d1, float& d2, float& d3,
                                         unsigned a0, unsigned a1, unsigned a2, unsigned a3,
                                         unsigned b0, unsigned b1)
{
    asm volatile(
        "mma.sync.aligned.m16n8k16.row.col.f32.bf16.bf16.f32 "
        "{%0,%1,%2,%3}, {%4,%5,%6,%7}, {%8,%9}, {%0,%1,%2,%3};\n"
        : "+f"(d0), "+f"(d1), "+f"(d2), "+f"(d3)
        : "r"(a0), "r"(a1), "r"(a2), "r"(a3), "r"(b0), "r"(b1));
}

// round-to-nearest-even fp32 -> bf16 (upper 16 bits)
__device__ __forceinline__ unsigned short f2bf(float x)
{
    unsigned u = __float_as_uint(x);
    u += 0x7FFFu + ((u >> 16) & 1u);
    return (unsigned short)(u >> 16);
}
__device__ __forceinline__ float bf2f(unsigned short h)
{
    return __uint_as_float(((unsigned)h) << 16);
}

#define KW 16          /* 32 k-values = 16 packed words per row */
#define SSTR 17        /* padded row stride in words */

__global__ __launch_bounds__(256)
void gemm_proj_tc_kernel(const float* __restrict__ A,
                         const float* __restrict__ W,
                         const float* __restrict__ bias,
                         float* __restrict__ out)
{
    __shared__ unsigned As_hi[128 * SSTR];
    __shared__ unsigned As_lo[128 * SSTR];
    __shared__ unsigned Bs_hi[128 * SSTR];
    __shared__ unsigned Bs_lo[128 * SSTR];

    const int tid = threadIdx.x;
    const int m0 = blockIdx.y * 128;
    const int n0 = blockIdx.x * 128;

    const int lrow = tid >> 1;          // 0..127
    const int ks   = (tid & 1) * 16;    // 0 or 16 (k offset within BK=32)

    const int lane = tid & 31;
    const int warp = tid >> 5;
    const int wm = warp >> 1;           // 0..3
    const int wn = warp & 1;            // 0..1
    const int qr = lane >> 2;           // 0..7
    const int qc = lane & 3;            // 0..3
    const int rA = wm * 32;
    const int cB = wn * 64;

    float acc[2][8][4];
#pragma unroll
    for (int mt = 0; mt < 2; mt++)
#pragma unroll
        for (int nt = 0; nt < 8; nt++)
#pragma unroll
            for (int e = 0; e < 4; e++) acc[mt][nt][e] = 0.0f;

    const float* Ap = A + (size_t)(m0 + lrow) * HIDD + ks;
    const float* Wp = W + (size_t)(n0 + lrow) * HIDD + ks;

    float4 ar[4], br[4];
#pragma unroll
    for (int j = 0; j < 4; j++) {
        ar[j] = *(const float4*)(Ap + j * 4);
        br[j] = *(const float4*)(Wp + j * 4);
    }

    for (int kt = 0; kt < HIDD; kt += 32) {
        __syncthreads();
        // convert + store the prefetched tile
        {
            unsigned* ah = As_hi + lrow * SSTR + (ks >> 1);
            unsigned* al = As_lo + lrow * SSTR + (ks >> 1);
            unsigned* bh = Bs_hi + lrow * SSTR + (ks >> 1);
            unsigned* bl = Bs_lo + lrow * SSTR + (ks >> 1);
#pragma unroll
            for (int j = 0; j < 4; j++) {
                float v0 = ar[j].x, v1 = ar[j].y, v2 = ar[j].z, v3 = ar[j].w;
                unsigned short h0 = f2bf(v0), h1 = f2bf(v1), h2 = f2bf(v2), h3 = f2bf(v3);
                unsigned short l0 = f2bf(v0 - bf2f(h0)), l1 = f2bf(v1 - bf2f(h1));
                unsigned short l2 = f2bf(v2 - bf2f(h2)), l3 = f2bf(v3 - bf2f(h3));
                ah[j * 2 + 0] = (unsigned)h0 | ((unsigned)h1 << 16);
                ah[j * 2 + 1] = (unsigned)h2 | ((unsigned)h3 << 16);
                al[j * 2 + 0] = (unsigned)l0 | ((unsigned)l1 << 16);
                al[j * 2 + 1] = (unsigned)l2 | ((unsigned)l3 << 16);

                v0 = br[j].x; v1 = br[j].y; v2 = br[j].z; v3 = br[j].w;
                h0 = f2bf(v0); h1 = f2bf(v1); h2 = f2bf(v2); h3 = f2bf(v3);
                l0 = f2bf(v0 - bf2f(h0)); l1 = f2bf(v1 - bf2f(h1));
                l2 = f2bf(v2 - bf2f(h2)); l3 = f2bf(v3 - bf2f(h3));
                bh[j * 2 + 0] = (unsigned)h0 | ((unsigned)h1 << 16);
                bh[j * 2 + 1] = (unsigned)h2 | ((unsigned)h3 << 16);
                bl[j * 2 + 0] = (unsigned)l0 | ((unsigned)l1 << 16);
                bl[j * 2 + 1] = (unsigned)l2 | ((unsigned)l3 << 16);
            }
        }
        __syncthreads();

        // prefetch next tile while computing this one
        if (kt + 32 < HIDD) {
#pragma unroll
            for (int j = 0; j < 4; j++) {
                ar[j] = *(const float4*)(Ap + kt + 32 + j * 4);
                br[j] = *(const float4*)(Wp + kt + 32 + j * 4);
            }
        }

#pragma unroll
        for (int s = 0; s < 2; s++) {
            const int kw0 = s * 8 + qc;
            unsigned a_hi[2][4], a_lo[2][4];
#pragma unroll
            for (int mt = 0; mt < 2; mt++) {
                int r0 = (rA + mt * 16 + qr) * SSTR;
                int r1 = (rA + mt * 16 + qr + 8) * SSTR;
                a_hi[mt][0] = As_hi[r0 + kw0];
                a_hi[mt][1] = As_hi[r1 + kw0];
                a_hi[mt][2] = As_hi[r0 + kw0 + 4];
                a_hi[mt][3] = As_hi[r1 + kw0 + 4];
                a_lo[mt][0] = As_lo[r0 + kw0];
                a_lo[mt][1] = As_lo[r1 + kw0];
                a_lo[mt][2] = As_lo[r0 + kw0 + 4];
                a_lo[mt][3] = As_lo[r1 + kw0 + 4];
            }
#pragma unroll
            for (int nt = 0; nt < 8; nt++) {
                int rb = (cB + nt * 8 + qr) * SSTR;
                unsigned b_hi0 = Bs_hi[rb + kw0];
                unsigned b_hi1 = Bs_hi[rb + kw0 + 4];
                unsigned b_lo0 = Bs_lo[rb + kw0];
                unsigned b_lo1 = Bs_lo[rb + kw0 + 4];
#pragma unroll
                for (int mt = 0; mt < 2; mt++) {
                    float* c = acc[mt][nt];
                    mma_bf16(c[0], c[1], c[2], c[3],
                             a_hi[mt][0], a_hi[mt][1], a_hi[mt][2], a_hi[mt][3],
                             b_hi0, b_hi1);
                    mma_bf16(c[0], c[1], c[2], c[3],
                             a_hi[mt][0], a_hi[mt][1], a_hi[mt][2], a_hi[mt][3],
                             b_lo0, b_lo1);
                    mma_bf16(c[0], c[1], c[2], c[3],
                             a_lo[mt][0], a_lo[mt][1], a_lo[mt][2], a_lo[mt][3],
                             b_hi0, b_hi1);
                }
            }
        }
    }

    // epilogue: add bias, remap flat (m, col) -> (n, h, t, d)
#pragma unroll
    for (int mt = 0; mt < 2; mt++) {
#pragma unroll
        for (int nt = 0; nt < 8; nt++) {
#pragma unroll
            for (int half = 0; half < 2; half++) {
                int row = m0 + rA + mt * 16 + qr + half * 8;
                int nb  = row >> 12;
                int t   = row & (TT - 1);
                int col = n0 + cB + nt * 8 + qc * 2;
                int h = col >> 6;
                int d = col & 63;
                float* op = out + (((size_t)(nb * NHH + h)) * TT + t) * DD + d;
                op[0] = acc[mt][nt][half * 2 + 0] + bias[col];
                op[1] = acc[mt][nt][half * 2 + 1] + bias[col + 1];
            }
        }
    }
}

// ---------------- norm-based top-k selection per 64-token block -------------------
__global__ void select_kernel(const float* __restrict__ mask,
                              const float* __restrict__ bq)
{
    const int blk = blockIdx.x;   // 0..63
    const int h   = blockIdx.y;
    const int n   = blockIdx.z;
    const int i   = threadIdx.x;  // 0..63
    __shared__ float norms[64];
    __shared__ int flags[64];

    const int token = blk * 64 + i;
    const float* kr = g_k + (((size_t)(n * NHH + h)) * TT + token) * DD;
    const float* bqr = bq + h * DD;
    float s = 0.0f;
#pragma unroll
    for (int d = 0; d < DD; d++) { float vv = kr[d] + bqr[d]; s += vv * vv; }
    if (mask[n * TT + token] != 0.0f) s = 0.0f;   // valid = (mask == 0)
    norms[i] = s;
    __syncthreads();

    // stable ascending argsort rank
    float mine = norms[i];
    int rank = 0;
    for (int j = 0; j < 64; j++) {
        float nj = norms[j];
        rank += (nj < mine) || (nj == mine && j < i);
    }
    int top = (rank >= 64 - TOPKK) ? 1 : 0;
    flags[i] = top;
    __syncthreads();

    int pos = 0;
    for (int j = 0; j < i; j++) pos += flags[j];
    if (top)
        g_gidx[((size_t)(n * NHH + h)) * (TT / 4) + blk * TOPKK + pos] = token;
    else
        g_lidx[((size_t)(n * NHH + h)) * (3 * TT / 4) + blk * 48 + (i - pos)] = token;
}

// ---------------- global pass: 64 queries x 48 gathered keys ----------------------
__global__ void attn_global_kernel(const float* __restrict__ mask)
{
    const int qb = blockIdx.x;    // 0..63
    const int h  = blockIdx.y;
    const int n  = blockIdx.z;
    const int tid = threadIdx.x;  // 64 threads
    __shared__ float ks[48 * 64];
    __shared__ float vs[48 * 64];
    __shared__ float ms[48];
    __shared__ float sc[64 * 49]; // padded stride 49

    const size_t ho = (size_t)(n * NHH + h);
    const float* kb = g_k + ho * TT * DD;
    const float* vb = g_v + ho * TT * DD;
    const int* gix = g_gidx + ho * (TT / 4);

    for (int idx = tid; idx < 48 * 64; idx += 64) {
        int r = idx >> 6, c = idx & 63;
        int g = qb * 16 - 16 + r;
        float kvv = 0.0f, vvv = 0.0f;
        if (g >= 0 && g < TT / 4) {
            int src = gix[g];
            kvv = kb[(size_t)src * DD + c];
            vvv = vb[(size_t)src * DD + c];
            if (c == 0) ms[r] = mask[n * TT + src];
        } else {
            if (c == 0) ms[r] = NEGV;
        }
        ks[idx] = kvv; vs[idx] = vvv;
    }
    __syncthreads();

    const int qi = tid;
    const int tq = qb * 64 + qi;
    const float* qr = g_q + (ho * TT + tq) * DD;
    float qreg[64];
#pragma unroll
    for (int d = 0; d < 64; d++) qreg[d] = qr[d];

    float* row = sc + qi * 49;
    float mmax = -1e30f;
    for (int kk = 0; kk < 48; kk++) {
        float dot = 0.0f;
#pragma unroll
        for (int d = 0; d < 64; d++) dot = fmaf(qreg[d], ks[kk * 64 + d], dot);
        float s = dot * 0.125f + ms[kk];
        row[kk] = s;
        mmax = fmaxf(mmax, s);
    }
    float l = 0.0f;
    for (int kk = 0; kk < 48; kk++) {
        float p = __expf(row[kk] - mmax);
        row[kk] = p;
        l += p;
    }
    g_lseg[ho * TT + tq] = mmax + logf(l);
    float inv = 1.0f / l;
    float* ctxr = g_ctxg + (ho * TT + tq) * DD;
    for (int d0 = 0; d0 < 64; d0 += 32) {
        float acc[32];
#pragma unroll
        for (int dd = 0; dd < 32; dd++) acc[dd] = 0.0f;
        for (int kk = 0; kk < 48; kk++) {
            float w = row[kk];
#pragma unroll
            for (int dd = 0; dd < 32; dd++)
                acc[dd] = fmaf(w, vs[kk * 64 + d0 + dd], acc[dd]);
        }
#pragma unroll
        for (int dd = 0; dd < 32; dd++) ctxr[d0 + dd] = acc[dd] * inv;
    }
}

// ---------------- local pass (flash, 2 threads/query) + merge + output ------------
__global__ void attn_local_kernel(const float* __restrict__ mask,
                                  float* __restrict__ out)
{
    extern __shared__ float sm[];
    float* ks = sm;                // WK*64
    float* vs = sm + WK * 64;      // WK*64
    float* ms = sm + 2 * WK * 64;  // WK

    const int qb = blockIdx.x;     // 0..31
    const int h  = blockIdx.y;
    const int n  = blockIdx.z;
    const int tid = threadIdx.x;   // 256

    const size_t ho = (size_t)(n * NHH + h);
    const float* kb = g_k + ho * TT * DD;
    const float* vb = g_v + ho * TT * DD;
    const int* lix = g_lidx + ho * (3 * TT / 4);

    for (int idx = tid; idx < WK * 64; idx += 256) {
        int r = idx >> 6, c = idx & 63;
        float kvv, vvv;
        if (r == 288) {            // appended global token (k[...,0,:], mask 0)
            kvv = kb[c]; vvv = vb[c];
            if (c == 0) ms[r] = 0.0f;
        } else {
            int g = qb * 96 - 96 + r;
            if (g >= 0 && g < 3 * TT / 4) {
                int src = lix[g];
                kvv = kb[(size_t)src * DD + c];
                vvv = vb[(size_t)src * DD + c];
                if (c == 0) ms[r] = mask[n * TT + src];
            } else {
                kvv = 0.0f; vvv = 0.0f;
                if (c == 0) ms[r] = NEGV;
            }
        }
        ks[idx] = kvv; vs[idx] = vvv;
    }
    __syncthreads();

    const int qi = tid >> 1;
    const int half = tid & 1;
    const int d0 = half * 32;
    const int tq = qb * 128 + qi;
    const float* qr = g_q + (ho * TT + tq) * DD + d0;
    float qreg[32];
#pragma unroll
    for (int dd = 0; dd < 32; dd++) qreg[dd] = qr[dd];

    float m = -1e30f, l = 0.0f;
    float ctx[32];
#pragma unroll
    for (int dd = 0; dd < 32; dd++) ctx[dd] = 0.0f;

    for (int kk = 0; kk < WK; kk++) {
        const float* krow = ks + kk * 64 + d0;
        float part = 0.0f;
#pragma unroll
        for (int dd = 0; dd < 32; dd++) part = fmaf(qreg[dd], krow[dd], part);
        float dot = part + __shfl_xor_sync(0xffffffffu, part, 1);
        float s = dot * 0.125f + ms[kk];
        float mn = fmaxf(m, s);
        float corr = __expf(m - mn);
        float p = __expf(s - mn);
        l = l * corr + p;
        const float* vrow = vs + kk * 64 + d0;
#pragma unroll
        for (int dd = 0; dd < 32; dd++)
            ctx[dd] = fmaf(ctx[dd], corr, p * vrow[dd]);
        m = mn;
    }

    float lse_l = m + logf(l);
    float lg = g_lseg[ho * TT + tq];
    float pm = 1.0f / (1.0f + __expf(lg - lse_l));
    float invl = 1.0f / l;
    const float* cg = g_ctxg + (ho * TT + tq) * DD + d0;
    float* op = out + ((size_t)n * TT + tq) * HIDD + h * DD + d0;
#pragma unroll
    for (int dd = 0; dd < 32; dd++) {
        float cl = ctx[dd] * invl;
        float cgv = cg[dd];
        op[dd] = cgv + pm * (cl - cgv);
    }
}

// ---------------- BOS row: full unscaled attention over all keys ------------------
__global__ void bos_kernel(const float* __restrict__ mask,
                           float* __restrict__ out)
{
    const int h = blockIdx.x;
    const int n = blockIdx.y;
    const int tid = threadIdx.x;   // 128
    __shared__ float sc[TT];
    __shared__ float qs[64];
    __shared__ float red[128];

    const size_t ho = (size_t)(n * NHH + h);
    const float* kb = g_k + ho * TT * DD;
    const float* vb = g_v + ho * TT * DD;
    if (tid < 64) qs[tid] = g_q[(ho * TT) * DD + tid];
    __syncthreads();

    float lmax = -1e30f;
    for (int t = tid; t < TT; t += 128) {
        const float* kr = kb + (size_t)t * DD;
        float dot = 0.0f;
#pragma unroll
        for (int d = 0; d < 64; d++) dot = fmaf(qs[d], kr[d], dot);
        float s = dot + mask[n * TT + t];   // NOTE: no 1/sqrt(d) scale for BOS
        sc[t] = s;
        lmax = fmaxf(lmax, s);
    }
    red[tid] = lmax;
    __syncthreads();
    for (int off = 64; off > 0; off >>= 1) {
        if (tid < off) red[tid] = fmaxf(red[tid], red[tid + off]);
        __syncthreads();
    }
    float mmax = red[0];
    float lsum = 0.0f;
    for (int t = tid; t < TT; t += 128) {
        float p = __expf(sc[t] - mmax);
        sc[t] = p;
        lsum += p;
    }
    __syncthreads();              // everyone has read red[0]
    red[tid] = lsum;
    __syncthreads();
    for (int off = 64; off > 0; off >>= 1) {
        if (tid < off) red[tid] += red[tid + off];
        __syncthreads();
    }
    float inv = 1.0f / red[0];
    if (tid < 64) {
        int d = tid;
        float acc = 0.0f;
        for (int t = 0; t < TT; t++)
            acc = fmaf(sc[t], vb[(size_t)t * DD + d], acc);
        out[((size_t)n * TT) * HIDD + h * DD + d] = acc * inv;
    }
}

// ---------------- launch ----------------------------------------------------------
extern "C" void kernel_launch(void* const* d_in, const int* in_sizes, int n_in,
                              void* d_out, int out_size)
{
    (void)in_sizes; (void)n_in; (void)out_size;
    const float* hs   = (const float*)d_in[0];
    const float* mask = (const float*)d_in[1];
    const float* Wq   = (const float*)d_in[2];
    const float* bq   = (const float*)d_in[3];
    const float* Wk   = (const float*)d_in[4];
    const float* bk   = (const float*)d_in[5];
    const float* Wv   = (const float*)d_in[6];
    const float* bv   = (const float*)d_in[7];
    float* out = (float*)d_out;

    float *qp, *kp, *vp;
    cudaGetSymbolAddress((void**)&qp, g_q);
    cudaGetSymbolAddress((void**)&kp, g_k);
    cudaGetSymbolAddress((void**)&vp, g_v);

    dim3 ggrid(HIDD / 128, (NB * TT) / 128);   // (8, 64)
    gemm_proj_tc_kernel<<<ggrid, 256>>>(hs, Wq, bq, qp);
    gemm_proj_tc_kernel<<<ggrid, 256>>>(hs, Wk, bk, kp);
    gemm_proj_tc_kernel<<<ggrid, 256>>>(hs, Wv, bv, vp);

    select_kernel<<<dim3(TT / 64, NHH, NB), 64>>>(mask, bq);

    attn_global_kernel<<<dim3(TT / 64, NHH, NB), 64>>>(mask);

    size_t lsmem = (size_t)(2 * WK * 64 + WK) * sizeof(float);   // ~149 KB
    cudaFuncSetAttribute(attn_local_kernel,
                         cudaFuncAttributeMaxDynamicSharedMemorySize, (int)lsmem);
    attn_local_kernel<<<dim3(TT / 128, NHH, NB), 256, lsmem>>>(mask, out);

    bos_kernel<<<dim3(NHH, NB), 128>>>(mask, out);
}

// round 3
// speedup vs baseline: 1.6875x; 1.3790x over previous
#include <cuda_runtime.h>
#include <cuda_bf16.h>
#include <math.h>

#define NB   2
#define TT   4096
#define HIDD 1024
#define NHH  16
#define DD   64
#define TOPKK 16
#define NEGV (-10000.0f)
#define WK   289   /* 3*96 local window + 1 global token */

// ---------------- device scratch ----------------
__device__ float g_q[(size_t)NB*NHH*TT*DD];
__device__ float g_k[(size_t)NB*NHH*TT*DD];
__device__ float g_v[(size_t)NB*NHH*TT*DD];
__device__ float g_ctxg[(size_t)NB*NHH*TT*DD];
__device__ float g_lseg[(size_t)NB*NHH*TT];
__device__ int   g_gidx[(size_t)NB*NHH*(TT/4)];
__device__ int   g_lidx[(size_t)NB*NHH*(3*TT/4)];

// ================= split-bf16 tensor-core GEMM: out = X @ W^T + b ================
__device__ __forceinline__ void mma_bf16(float& d0, float& d1, float& d2, float& d3,
                                         unsigned a0, unsigned a1, unsigned a2, unsigned a3,
                                         unsigned b0, unsigned b1)
{
    asm volatile(
        "mma.sync.aligned.m16n8k16.row.col.f32.bf16.bf16.f32 "
        "{%0,%1,%2,%3}, {%4,%5,%6,%7}, {%8,%9}, {%0,%1,%2,%3};\n"
        : "+f"(d0), "+f"(d1), "+f"(d2), "+f"(d3)
        : "r"(a0), "r"(a1), "r"(a2), "r"(a3), "r"(b0), "r"(b1));
}

__device__ __forceinline__ unsigned short f2bf(float x)
{
    unsigned u = __float_as_uint(x);
    u += 0x7FFFu + ((u >> 16) & 1u);
    return (unsigned short)(u >> 16);
}
__device__ __forceinline__ float bf2f(unsigned short h)
{
    return __uint_as_float(((unsigned)h) << 16);
}

#define SSTR 17

__global__ __launch_bounds__(256)
void gemm_proj_tc_kernel(const float* __restrict__ A,
                         const float* __restrict__ W,
                         const float* __restrict__ bias,
                         float* __restrict__ out)
{
    __shared__ unsigned As_hi[128 * SSTR];
    __shared__ unsigned As_lo[128 * SSTR];
    __shared__ unsigned Bs_hi[128 * SSTR];
    __shared__ unsigned Bs_lo[128 * SSTR];

    const int tid = threadIdx.x;
    const int m0 = blockIdx.y * 128;
    const int n0 = blockIdx.x * 128;

    const int lrow = tid >> 1;
    const int ks   = (tid & 1) * 16;

    const int lane = tid & 31;
    const int warp = tid >> 5;
    const int wm = warp >> 1;
    const int wn = warp & 1;
    const int qr = lane >> 2;
    const int qc = lane & 3;
    const int rA = wm * 32;
    const int cB = wn * 64;

    float acc[2][8][4];
#pragma unroll
    for (int mt = 0; mt < 2; mt++)
#pragma unroll
        for (int nt = 0; nt < 8; nt++)
#pragma unroll
            for (int e = 0; e < 4; e++) acc[mt][nt][e] = 0.0f;

    const float* Ap = A + (size_t)(m0 + lrow) * HIDD + ks;
    const float* Wp = W + (size_t)(n0 + lrow) * HIDD + ks;

    float4 ar[4], br[4];
#pragma unroll
    for (int j = 0; j < 4; j++) {
        ar[j] = *(const float4*)(Ap + j * 4);
        br[j] = *(const float4*)(Wp + j * 4);
    }

    for (int kt = 0; kt < HIDD; kt += 32) {
        __syncthreads();
        {
            unsigned* ah = As_hi + lrow * SSTR + (ks >> 1);
            unsigned* al = As_lo + lrow * SSTR + (ks >> 1);
            unsigned* bh = Bs_hi + lrow * SSTR + (ks >> 1);
            unsigned* bl = Bs_lo + lrow * SSTR + (ks >> 1);
#pragma unroll
            for (int j = 0; j < 4; j++) {
                float v0 = ar[j].x, v1 = ar[j].y, v2 = ar[j].z, v3 = ar[j].w;
                unsigned short h0 = f2bf(v0), h1 = f2bf(v1), h2 = f2bf(v2), h3 = f2bf(v3);
                unsigned short l0 = f2bf(v0 - bf2f(h0)), l1 = f2bf(v1 - bf2f(h1));
                unsigned short l2 = f2bf(v2 - bf2f(h2)), l3 = f2bf(v3 - bf2f(h3));
                ah[j * 2 + 0] = (unsigned)h0 | ((unsigned)h1 << 16);
                ah[j * 2 + 1] = (unsigned)h2 | ((unsigned)h3 << 16);
                al[j * 2 + 0] = (unsigned)l0 | ((unsigned)l1 << 16);
                al[j * 2 + 1] = (unsigned)l2 | ((unsigned)l3 << 16);

                v0 = br[j].x; v1 = br[j].y; v2 = br[j].z; v3 = br[j].w;
                h0 = f2bf(v0); h1 = f2bf(v1); h2 = f2bf(v2); h3 = f2bf(v3);
                l0 = f2bf(v0 - bf2f(h0)); l1 = f2bf(v1 - bf2f(h1));
                l2 = f2bf(v2 - bf2f(h2)); l3 = f2bf(v3 - bf2f(h3));
                bh[j * 2 + 0] = (unsigned)h0 | ((unsigned)h1 << 16);
                bh[j * 2 + 1] = (unsigned)h2 | ((unsigned)h3 << 16);
                bl[j * 2 + 0] = (unsigned)l0 | ((unsigned)l1 << 16);
                bl[j * 2 + 1] = (unsigned)l2 | ((unsigned)l3 << 16);
            }
        }
        __syncthreads();

        if (kt + 32 < HIDD) {
#pragma unroll
            for (int j = 0; j < 4; j++) {
                ar[j] = *(const float4*)(Ap + kt + 32 + j * 4);
                br[j] = *(const float4*)(Wp + kt + 32 + j * 4);
            }
        }

#pragma unroll
        for (int s = 0; s < 2; s++) {
            const int kw0 = s * 8 + qc;
            unsigned a_hi[2][4], a_lo[2][4];
#pragma unroll
            for (int mt = 0; mt < 2; mt++) {
                int r0 = (rA + mt * 16 + qr) * SSTR;
                int r1 = (rA + mt * 16 + qr + 8) * SSTR;
                a_hi[mt][0] = As_hi[r0 + kw0];
                a_hi[mt][1] = As_hi[r1 + kw0];
                a_hi[mt][2] = As_hi[r0 + kw0 + 4];
                a_hi[mt][3] = As_hi[r1 + kw0 + 4];
                a_lo[mt][0] = As_lo[r0 + kw0];
                a_lo[mt][1] = As_lo[r1 + kw0];
                a_lo[mt][2] = As_lo[r0 + kw0 + 4];
                a_lo[mt][3] = As_lo[r1 + kw0 + 4];
            }
#pragma unroll
            for (int nt = 0; nt < 8; nt++) {
                int rb = (cB + nt * 8 + qr) * SSTR;
                unsigned b_hi0 = Bs_hi[rb + kw0];
                unsigned b_hi1 = Bs_hi[rb + kw0 + 4];
                unsigned b_lo0 = Bs_lo[rb + kw0];
                unsigned b_lo1 = Bs_lo[rb + kw0 + 4];
#pragma unroll
                for (int mt = 0; mt < 2; mt++) {
                    float* c = acc[mt][nt];
                    mma_bf16(c[0], c[1], c[2], c[3],
                             a_hi[mt][0], a_hi[mt][1], a_hi[mt][2], a_hi[mt][3],
                             b_hi0, b_hi1);
                    mma_bf16(c[0], c[1], c[2], c[3],
                             a_hi[mt][0], a_hi[mt][1], a_hi[mt][2], a_hi[mt][3],
                             b_lo0, b_lo1);
                    mma_bf16(c[0], c[1], c[2], c[3],
                             a_lo[mt][0], a_lo[mt][1], a_lo[mt][2], a_lo[mt][3],
                             b_hi0, b_hi1);
                }
            }
        }
    }

#pragma unroll
    for (int mt = 0; mt < 2; mt++) {
#pragma unroll
        for (int nt = 0; nt < 8; nt++) {
#pragma unroll
            for (int half = 0; half < 2; half++) {
                int row = m0 + rA + mt * 16 + qr + half * 8;
                int nb  = row >> 12;
                int t   = row & (TT - 1);
                int col = n0 + cB + nt * 8 + qc * 2;
                int h = col >> 6;
                int d = col & 63;
                float* op = out + (((size_t)(nb * NHH + h)) * TT + t) * DD + d;
                op[0] = acc[mt][nt][half * 2 + 0] + bias[col];
                op[1] = acc[mt][nt][half * 2 + 1] + bias[col + 1];
            }
        }
    }
}

// ---------------- norm-based top-k selection per 64-token block -------------------
__global__ void select_kernel(const float* __restrict__ mask,
                              const float* __restrict__ bq)
{
    const int blk = blockIdx.x;
    const int h   = blockIdx.y;
    const int n   = blockIdx.z;
    const int i   = threadIdx.x;
    __shared__ float norms[64];
    __shared__ int flags[64];

    const int token = blk * 64 + i;
    const float* kr = g_k + (((size_t)(n * NHH + h)) * TT + token) * DD;
    const float* bqr = bq + h * DD;
    float s = 0.0f;
#pragma unroll
    for (int d = 0; d < DD; d++) { float vv = kr[d] + bqr[d]; s += vv * vv; }
    if (mask[n * TT + token] != 0.0f) s = 0.0f;
    norms[i] = s;
    __syncthreads();

    float mine = norms[i];
    int rank = 0;
    for (int j = 0; j < 64; j++) {
        float nj = norms[j];
        rank += (nj < mine) || (nj == mine && j < i);
    }
    int top = (rank >= 64 - TOPKK) ? 1 : 0;
    flags[i] = top;
    __syncthreads();

    int pos = 0;
    for (int j = 0; j < i; j++) pos += flags[j];
    if (top)
        g_gidx[((size_t)(n * NHH + h)) * (TT / 4) + blk * TOPKK + pos] = token;
    else
        g_lidx[((size_t)(n * NHH + h)) * (3 * TT / 4) + blk * 48 + (i - pos)] = token;
}

// ---------------- global pass: 64 queries x 48 gathered keys ----------------------
__global__ void attn_global_kernel(const float* __restrict__ mask)
{
    const int qb = blockIdx.x;
    const int h  = blockIdx.y;
    const int n  = blockIdx.z;
    const int tid = threadIdx.x;
    __shared__ float ks[48 * 64];
    __shared__ float vs[48 * 64];
    __shared__ float ms[48];
    __shared__ float sc[64 * 49];

    const size_t ho = (size_t)(n * NHH + h);
    const float* kb = g_k + ho * TT * DD;
    const float* vb = g_v + ho * TT * DD;
    const int* gix = g_gidx + ho * (TT / 4);

    for (int idx = tid; idx < 48 * 64; idx += 64) {
        int r = idx >> 6, c = idx & 63;
        int g = qb * 16 - 16 + r;
        float kvv = 0.0f, vvv = 0.0f;
        if (g >= 0 && g < TT / 4) {
            int src = gix[g];
            kvv = kb[(size_t)src * DD + c];
            vvv = vb[(size_t)src * DD + c];
            if (c == 0) ms[r] = mask[n * TT + src];
        } else {
            if (c == 0) ms[r] = NEGV;
        }
        ks[idx] = kvv; vs[idx] = vvv;
    }
    __syncthreads();

    const int qi = tid;
    const int tq = qb * 64 + qi;
    const float* qr = g_q + (ho * TT + tq) * DD;
    float qreg[64];
#pragma unroll
    for (int d = 0; d < 64; d++) qreg[d] = qr[d];

    float* row = sc + qi * 49;
    float mmax = -1e30f;
    for (int kk = 0; kk < 48; kk++) {
        float dot = 0.0f;
#pragma unroll
        for (int d = 0; d < 64; d++) dot = fmaf(qreg[d], ks[kk * 64 + d], dot);
        float s = dot * 0.125f + ms[kk];
        row[kk] = s;
        mmax = fmaxf(mmax, s);
    }
    float l = 0.0f;
    for (int kk = 0; kk < 48; kk++) {
        float p = __expf(row[kk] - mmax);
        row[kk] = p;
        l += p;
    }
    g_lseg[ho * TT + tq] = mmax + logf(l);
    float inv = 1.0f / l;
    float* ctxr = g_ctxg + (ho * TT + tq) * DD;
    for (int d0 = 0; d0 < 64; d0 += 32) {
        float acc[32];
#pragma unroll
        for (int dd = 0; dd < 32; dd++) acc[dd] = 0.0f;
        for (int kk = 0; kk < 48; kk++) {
            float w = row[kk];
#pragma unroll
            for (int dd = 0; dd < 32; dd++)
                acc[dd] = fmaf(w, vs[kk * 64 + d0 + dd], acc[dd]);
        }
#pragma unroll
        for (int dd = 0; dd < 32; dd++) ctxr[d0 + dd] = acc[dd] * inv;
    }
}

// ============== local pass: tf32 tensor-core flash + merge + output ===============
// Per block (qb,h,n): Q 128x64, keys = 289 shared window (+pad to 336), 3 chunks of 112.
// 8 warps, each owns 16 query rows. S = Q*K^T via m16n8k8 tf32; online softmax
// (intra-warp); P staged in smem (per-warp rows, layout fix for A-frag); O = P*V.

#define KC     112
#define NCHK   3
#define QSTRW  68     /* Q/K row stride (words) */
#define VSTRW  72     /* V row stride */
#define PSTRW  116    /* P row stride */
#define QS_OFF 0
#define KS_OFF (QS_OFF + 128*QSTRW)          /* 8704 */
#define VS_OFF (KS_OFF + KC*QSTRW)           /* 16320 */
#define PS_OFF (VS_OFF + KC*VSTRW)           /* 24384 */
#define MS_OFF (PS_OFF + 128*PSTRW)          /* 39232 */
#define LSMEM_WORDS (MS_OFF + KC)            /* 39344 */

__device__ __forceinline__ float to_tf32(float x)
{
    float r;
    asm("cvt.rna.tf32.f32 %0, %1;" : "=f"(r) : "f"(x));
    return r;
}

__device__ __forceinline__ void mma_tf32(float& d0, float& d1, float& d2, float& d3,
                                         float a0, float a1, float a2, float a3,
                                         float b0, float b1)
{
    asm volatile(
        "mma.sync.aligned.m16n8k8.row.col.f32.tf32.tf32.f32 "
        "{%0,%1,%2,%3}, {%4,%5,%6,%7}, {%8,%9}, {%0,%1,%2,%3};\n"
        : "+f"(d0), "+f"(d1), "+f"(d2), "+f"(d3)
        : "r"(__float_as_uint(a0)), "r"(__float_as_uint(a1)),
          "r"(__float_as_uint(a2)), "r"(__float_as_uint(a3)),
          "r"(__float_as_uint(b0)), "r"(__float_as_uint(b1)));
}

__global__ __launch_bounds__(256)
void attn_local_tc_kernel(const float* __restrict__ mask,
                          float* __restrict__ out)
{
    extern __shared__ float sm[];
    float* Qs = sm + QS_OFF;
    float* Ks = sm + KS_OFF;
    float* Vs = sm + VS_OFF;
    float* Ps = sm + PS_OFF;
    float* Ms = sm + MS_OFF;

    const int qb = blockIdx.x;     // 0..31
    const int h  = blockIdx.y;
    const int n  = blockIdx.z;
    const int tid = threadIdx.x;
    const int lane = tid & 31;
    const int warp = tid >> 5;     // 0..7, owns rows warp*16..+15
    const int qr = lane >> 2;      // 0..7
    const int qc = lane & 3;       // 0..3
    const int w16 = warp * 16;

    const size_t ho = (size_t)(n * NHH + h);
    const float* kb = g_k + ho * TT * DD;
    const float* vb = g_v + ho * TT * DD;
    const int* lix = g_lidx + ho * (3 * TT / 4);

    // ---- load Q tile (tf32-rounded) ----
#pragma unroll
    for (int i = 0; i < 8; i++) {
        int idx = tid + i * 256;           // 0..2047
        int r = idx >> 4, c4 = idx & 15;
        const float4 qv = *(const float4*)(g_q + (ho * TT + qb * 128 + r) * DD + c4 * 4);
        float* dst = Qs + r * QSTRW + c4 * 4;
        dst[0] = to_tf32(qv.x); dst[1] = to_tf32(qv.y);
        dst[2] = to_tf32(qv.z); dst[3] = to_tf32(qv.w);
    }

    // ---- flash state ----
    float m0 = -1e30f, m1 = -1e30f, l0 = 0.0f, l1 = 0.0f;
    float o[8][4];
#pragma unroll
    for (int nt = 0; nt < 8; nt++)
#pragma unroll
        for (int e = 0; e < 4; e++) o[nt][e] = 0.0f;

    for (int ch = 0; ch < NCHK; ch++) {
        __syncthreads();   // previous chunk's PV done before overwriting K/V
        // ---- gather K/V chunk (tf32-rounded) ----
        for (int idx = tid; idx < KC * 16; idx += 256) {
            int r = idx >> 4, c4 = idx & 15;
            int kk = ch * KC + r;
            float4 kv = make_float4(0.f, 0.f, 0.f, 0.f);
            float4 vv = make_float4(0.f, 0.f, 0.f, 0.f);
            float mval = -1e30f;
            if (kk < 288) {
                int g = qb * 96 - 96 + kk;
                if (g >= 0 && g < 3 * TT / 4) {
                    int src = lix[g];
                    kv = *(const float4*)(kb + (size_t)src * DD + c4 * 4);
                    vv = *(const float4*)(vb + (size_t)src * DD + c4 * 4);
                    mval = mask[n * TT + src];
                } else {
                    mval = NEGV;
                }
            } else if (kk == 288) {        // appended global token
                kv = *(const float4*)(kb + c4 * 4);
                vv = *(const float4*)(vb + c4 * 4);
                mval = 0.0f;
            }
            float* kd = Ks + r * QSTRW + c4 * 4;
            kd[0] = to_tf32(kv.x); kd[1] = to_tf32(kv.y);
            kd[2] = to_tf32(kv.z); kd[3] = to_tf32(kv.w);
            float* vd = Vs + r * VSTRW + c4 * 4;
            vd[0] = to_tf32(vv.x); vd[1] = to_tf32(vv.y);
            vd[2] = to_tf32(vv.z); vd[3] = to_tf32(vv.w);
            if (c4 == 0) Ms[r] = mval;
        }
        __syncthreads();

        // ---- S = Q*K^T : 14 n-tiles x 8 k-steps ----
        float s[14][4];
#pragma unroll
        for (int nt = 0; nt < 14; nt++)
#pragma unroll
            for (int e = 0; e < 4; e++) s[nt][e] = 0.0f;

#pragma unroll
        for (int k8 = 0; k8 < 8; k8++) {
            const int kc0 = k8 * 8 + qc;
            float a0 = Qs[(w16 + qr) * QSTRW + kc0];
            float a1 = Qs[(w16 + qr + 8) * QSTRW + kc0];
            float a2 = Qs[(w16 + qr) * QSTRW + kc0 + 4];
            float a3 = Qs[(w16 + qr + 8) * QSTRW + kc0 + 4];
#pragma unroll
            for (int nt = 0; nt < 14; nt++) {
                float b0 = Ks[(nt * 8 + qr) * QSTRW + kc0];
                float b1 = Ks[(nt * 8 + qr) * QSTRW + kc0 + 4];
                mma_tf32(s[nt][0], s[nt][1], s[nt][2], s[nt][3],
                         a0, a1, a2, a3, b0, b1);
            }
        }

        // ---- scale + mask + chunk row-max ----
        float cmax0 = -1e30f, cmax1 = -1e30f;
#pragma unroll
        for (int nt = 0; nt < 14; nt++) {
            float mc0 = Ms[nt * 8 + 2 * qc];
            float mc1 = Ms[nt * 8 + 2 * qc + 1];
            s[nt][0] = s[nt][0] * 0.125f + mc0;
            s[nt][1] = s[nt][1] * 0.125f + mc1;
            s[nt][2] = s[nt][2] * 0.125f + mc0;
            s[nt][3] = s[nt][3] * 0.125f + mc1;
            cmax0 = fmaxf(cmax0, fmaxf(s[nt][0], s[nt][1]));
            cmax1 = fmaxf(cmax1, fmaxf(s[nt][2], s[nt][3]));
        }
        cmax0 = fmaxf(cmax0, __shfl_xor_sync(0xffffffffu, cmax0, 1));
        cmax0 = fmaxf(cmax0, __shfl_xor_sync(0xffffffffu, cmax0, 2));
        cmax1 = fmaxf(cmax1, __shfl_xor_sync(0xffffffffu, cmax1, 1));
        cmax1 = fmaxf(cmax1, __shfl_xor_sync(0xffffffffu, cmax1, 2));

        float mn0 = fmaxf(m0, cmax0);
        float mn1 = fmaxf(m1, cmax1);
        float corr0 = __expf(m0 - mn0);
        float corr1 = __expf(m1 - mn1);
        m0 = mn0; m1 = mn1;

        // ---- P = exp(S - m), row sums, stage P in smem ----
        float rs0 = 0.0f, rs1 = 0.0f;
#pragma unroll
        for (int nt = 0; nt < 14; nt++) {
            float p0 = __expf(s[nt][0] - mn0);
            float p1 = __expf(s[nt][1] - mn0);
            float p2 = __expf(s[nt][2] - mn1);
            float p3 = __expf(s[nt][3] - mn1);
            rs0 += p0 + p1; rs1 += p2 + p3;
            float* pr0 = Ps + (w16 + qr) * PSTRW + nt * 8 + 2 * qc;
            float* pr1 = Ps + (w16 + qr + 8) * PSTRW + nt * 8 + 2 * qc;
            pr0[0] = to_tf32(p0); pr0[1] = to_tf32(p1);
            pr1[0] = to_tf32(p2); pr1[1] = to_tf32(p3);
        }
        rs0 += __shfl_xor_sync(0xffffffffu, rs0, 1);
        rs0 += __shfl_xor_sync(0xffffffffu, rs0, 2);
        rs1 += __shfl_xor_sync(0xffffffffu, rs1, 1);
        rs1 += __shfl_xor_sync(0xffffffffu, rs1, 2);
        l0 = l0 * corr0 + rs0;
        l1 = l1 * corr1 + rs1;

        // ---- rescale O ----
#pragma unroll
        for (int nt = 0; nt < 8; nt++) {
            o[nt][0] *= corr0; o[nt][1] *= corr0;
            o[nt][2] *= corr1; o[nt][3] *= corr1;
        }
        __syncwarp();

        // ---- O += P * V : 14 k-steps x 8 n-tiles ----
#pragma unroll
        for (int kt = 0; kt < 14; kt++) {
            const int kc0 = kt * 8 + qc;
            float a0 = Ps[(w16 + qr) * PSTRW + kc0];
            float a1 = Ps[(w16 + qr + 8) * PSTRW + kc0];
            float a2 = Ps[(w16 + qr) * PSTRW + kc0 + 4];
            float a3 = Ps[(w16 + qr + 8) * PSTRW + kc0 + 4];
#pragma unroll
            for (int nt = 0; nt < 8; nt++) {
                float b0 = Vs[(kt * 8 + qc) * VSTRW + nt * 8 + qr];
                float b1 = Vs[(kt * 8 + qc + 4) * VSTRW + nt * 8 + qr];
                mma_tf32(o[nt][0], o[nt][1], o[nt][2], o[nt][3],
                         a0, a1, a2, a3, b0, b1);
            }
        }
    }

    // ---- epilogue: normalize, merge with global pass, write out ----
    float lse0 = m0 + logf(l0);
    float lse1 = m1 + logf(l1);
    float inv0 = 1.0f / l0;
    float inv1 = 1.0f / l1;

    int row0 = qb * 128 + w16 + qr;
    int row1 = row0 + 8;
    float lg0 = g_lseg[ho * TT + row0];
    float lg1 = g_lseg[ho * TT + row1];
    float pm0 = 1.0f / (1.0f + __expf(lg0 - lse0));
    float pm1 = 1.0f / (1.0f + __expf(lg1 - lse1));

    const float* cg0 = g_ctxg + (ho * TT + row0) * DD;
    const float* cg1 = g_ctxg + (ho * TT + row1) * DD;
    float* op0 = out + ((size_t)n * TT + row0) * HIDD + h * DD;
    float* op1 = out + ((size_t)n * TT + row1) * HIDD + h * DD;

#pragma unroll
    for (int nt = 0; nt < 8; nt++) {
        int c0 = nt * 8 + 2 * qc;
#pragma unroll
        for (int e = 0; e < 2; e++) {
            float cl0 = o[nt][e] * inv0;
            float cv0 = cg0[c0 + e];
            op0[c0 + e] = cv0 + pm0 * (cl0 - cv0);
            float cl1 = o[nt][2 + e] * inv1;
            float cv1 = cg1[c0 + e];
            op1[c0 + e] = cv1 + pm1 * (cl1 - cv1);
        }
    }
}

// ---------------- BOS row ---------------------------------------------------------
__global__ void bos_kernel(const float* __restrict__ mask,
                           float* __restrict__ out)
{
    const int h = blockIdx.x;
    const int n = blockIdx.y;
    const int tid = threadIdx.x;
    __shared__ float sc[TT];
    __shared__ float qs[64];
    __shared__ float red[128];

    const size_t ho = (size_t)(n * NHH + h);
    const float* kb = g_k + ho * TT * DD;
    const float* vb = g_v + ho * TT * DD;
    if (tid < 64) qs[tid] = g_q[(ho * TT) * DD + tid];
    __syncthreads();

    float lmax = -1e30f;
    for (int t = tid; t < TT; t += 128) {
        const float* kr = kb + (size_t)t * DD;
        float dot = 0.0f;
#pragma unroll
        for (int d = 0; d < 64; d++) dot = fmaf(qs[d], kr[d], dot);
        float s = dot + mask[n * TT + t];
        sc[t] = s;
        lmax = fmaxf(lmax, s);
    }
    red[tid] = lmax;
    __syncthreads();
    for (int off = 64; off > 0; off >>= 1) {
        if (tid < off) red[tid] = fmaxf(red[tid], red[tid + off]);
        __syncthreads();
    }
    float mmax = red[0];
    float lsum = 0.0f;
    for (int t = tid; t < TT; t += 128) {
        float p = __expf(sc[t] - mmax);
        sc[t] = p;
        lsum += p;
    }
    __syncthreads();
    red[tid] = lsum;
    __syncthreads();
    for (int off = 64; off > 0; off >>= 1) {
        if (tid < off) red[tid] += red[tid + off];
        __syncthreads();
    }
    float inv = 1.0f / red[0];
    if (tid < 64) {
        int d = tid;
        float acc = 0.0f;
        for (int t = 0; t < TT; t++)
            acc = fmaf(sc[t], vb[(size_t)t * DD + d], acc);
        out[((size_t)n * TT) * HIDD + h * DD + d] = acc * inv;
    }
}

// ---------------- launch ----------------------------------------------------------
extern "C" void kernel_launch(void* const* d_in, const int* in_sizes, int n_in,
                              void* d_out, int out_size)
{
    (void)in_sizes; (void)n_in; (void)out_size;
    const float* hs   = (const float*)d_in[0];
    const float* mask = (const float*)d_in[1];
    const float* Wq   = (const float*)d_in[2];
    const float* bq   = (const float*)d_in[3];
    const float* Wk   = (const float*)d_in[4];
    const float* bk   = (const float*)d_in[5];
    const float* Wv   = (const float*)d_in[6];
    const float* bv   = (const float*)d_in[7];
    float* out = (float*)d_out;

    float *qp, *kp, *vp;
    cudaGetSymbolAddress((void**)&qp, g_q);
    cudaGetSymbolAddress((void**)&kp, g_k);
    cudaGetSymbolAddress((void**)&vp, g_v);

    dim3 ggrid(HIDD / 128, (NB * TT) / 128);
    gemm_proj_tc_kernel<<<ggrid, 256>>>(hs, Wq, bq, qp);
    gemm_proj_tc_kernel<<<ggrid, 256>>>(hs, Wk, bk, kp);
    gemm_proj_tc_kernel<<<ggrid, 256>>>(hs, Wv, bv, vp);

    select_kernel<<<dim3(TT / 64, NHH, NB), 64>>>(mask, bq);

    attn_global_kernel<<<dim3(TT / 64, NHH, NB), 64>>>(mask);

    size_t lsmem = (size_t)LSMEM_WORDS * sizeof(float);   // ~153.7 KB
    cudaFuncSetAttribute(attn_local_tc_kernel,
                         cudaFuncAttributeMaxDynamicSharedMemorySize, (int)lsmem);
    attn_local_tc_kernel<<<dim3(TT / 128, NHH, NB), 256, lsmem>>>(mask, out);

    bos_kernel<<<dim3(NHH, NB), 128>>>(mask, out);
}

// round 6
// speedup vs baseline: 2.3617x; 1.3995x over previous
#include <cuda_runtime.h>
#include <cuda_bf16.h>
#include <math.h>

#define NB   2
#define TT   4096
#define HIDD 1024
#define NHH  16
#define DD   64
#define TOPKK 16
#define NEGV (-10000.0f)

// ---------------- device scratch ----------------
__device__ float g_q[(size_t)NB*NHH*TT*DD];
__device__ float g_k[(size_t)NB*NHH*TT*DD];
__device__ float g_v[(size_t)NB*NHH*TT*DD];
__device__ float g_ctxg[(size_t)NB*NHH*TT*DD];
__device__ float g_lseg[(size_t)NB*NHH*TT];
__device__ int   g_gidx[(size_t)NB*NHH*(TT/4)];
__device__ int   g_lidx[(size_t)NB*NHH*(3*TT/4)];
// split-bf16 planes — uint4-typed so the base is 16-byte aligned
__device__ uint4 g_Ahi4[(size_t)NB*TT*HIDD/8];
__device__ uint4 g_Alo4[(size_t)NB*TT*HIDD/8];
__device__ uint4 g_Whi4[(size_t)3*HIDD*HIDD/8];
__device__ uint4 g_Wlo4[(size_t)3*HIDD*HIDD/8];

// ---------------- helpers ----------------
__device__ __forceinline__ unsigned short f2bf(float x)
{
    unsigned u = __float_as_uint(x);
    u += 0x7FFFu + ((u >> 16) & 1u);
    return (unsigned short)(u >> 16);
}
__device__ __forceinline__ float bf2f(unsigned short h)
{
    return __uint_as_float(((unsigned)h) << 16);
}

__device__ __forceinline__ void mma_bf16(float& d0, float& d1, float& d2, float& d3,
                                         unsigned a0, unsigned a1, unsigned a2, unsigned a3,
                                         unsigned b0, unsigned b1)
{
    asm volatile(
        "mma.sync.aligned.m16n8k16.row.col.f32.bf16.bf16.f32 "
        "{%0,%1,%2,%3}, {%4,%5,%6,%7}, {%8,%9}, {%0,%1,%2,%3};\n"
        : "+f"(d0), "+f"(d1), "+f"(d2), "+f"(d3)
        : "r"(a0), "r"(a1), "r"(a2), "r"(a3), "r"(b0), "r"(b1));
}

__device__ __forceinline__ void cp16(void* smem_dst, const void* gsrc)
{
    unsigned saddr = (unsigned)__cvta_generic_to_shared(smem_dst);
    asm volatile("cp.async.ca.shared.global [%0], [%1], 16;\n"
                 :: "r"(saddr), "l"(gsrc));
}
__device__ __forceinline__ void cp_commit()
{
    asm volatile("cp.async.commit_group;\n" ::: "memory");
}
template <int N> __device__ __forceinline__ void cp_wait()
{
    asm volatile("cp.async.wait_group %0;\n" :: "n"(N) : "memory");
}

// ---------------- split conversion: fp32 -> hi/lo bf16 planes ---------------------
__global__ void cvt_split_kernel(const float* __restrict__ in,
                                 uint2* __restrict__ hi,
                                 uint2* __restrict__ lo, int n4)
{
    int i = blockIdx.x * blockDim.x + threadIdx.x;
    if (i >= n4) return;
    float4 v = ((const float4*)in)[i];
    unsigned short h0 = f2bf(v.x), h1 = f2bf(v.y), h2 = f2bf(v.z), h3 = f2bf(v.w);
    unsigned short l0 = f2bf(v.x - bf2f(h0)), l1 = f2bf(v.y - bf2f(h1));
    unsigned short l2 = f2bf(v.z - bf2f(h2)), l3 = f2bf(v.w - bf2f(h3));
    hi[i] = make_uint2((unsigned)h0 | ((unsigned)h1 << 16),
                       (unsigned)h2 | ((unsigned)h3 << 16));
    lo[i] = make_uint2((unsigned)l0 | ((unsigned)l1 << 16),
                       (unsigned)l2 | ((unsigned)l3 << 16));
}

// ============= fused QKV GEMM: out_z = X @ Wz^T + bz  (split-bf16, cp.async) ======
// Tiles 128x128x32, 256 threads (8 warps 4m x 2n), double-buffered smem.
// Row stride 20 words = 80 bytes: multiple of 16 (cp.async smem-dst alignment!)
// and conflict-free for the MMA fragment LDS pattern (20*qr+qc distinct mod 32).
#define GSTR 20                       /* row stride in words */
#define PLW  (128 * GSTR)             /* words per plane = 2560 */
#define PA_HI 0
#define PA_LO (1 * PLW)
#define PB_HI (2 * PLW)
#define PB_LO (3 * PLW)
#define STGW  (4 * PLW)               /* words per stage = 10240 (40KB) */

__device__ __forceinline__ void gemm_load_stage(unsigned* st,
                                                const __nv_bfloat16* Ah,
                                                const __nv_bfloat16* Al,
                                                const __nv_bfloat16* Wh,
                                                const __nv_bfloat16* Wl,
                                                int kofs, int tid)
{
#pragma unroll
    for (int i = 0; i < 2; i++) {
        int c = tid + i * 256;        // 0..511
        int row = c >> 2;
        int cw = c & 3;
        size_t go = (size_t)row * HIDD + kofs + cw * 8;
        unsigned* sp = st + row * GSTR + cw * 4;
        cp16(sp + PA_HI, Ah + go);
        cp16(sp + PA_LO, Al + go);
        cp16(sp + PB_HI, Wh + go);
        cp16(sp + PB_LO, Wl + go);
    }
    cp_commit();
}

__global__ __launch_bounds__(256, 2)
void gemm_qkv_kernel(const float* __restrict__ bq,
                     const float* __restrict__ bk,
                     const float* __restrict__ bv,
                     float* __restrict__ oq,
                     float* __restrict__ ok,
                     float* __restrict__ ov)
{
    extern __shared__ unsigned gsm[];

    const int tid = threadIdx.x;
    const int m0 = blockIdx.y * 128;
    const int n0 = blockIdx.x * 128;
    const int z  = blockIdx.z;

    const __nv_bfloat16* Ah = (const __nv_bfloat16*)g_Ahi4 + (size_t)m0 * HIDD;
    const __nv_bfloat16* Al = (const __nv_bfloat16*)g_Alo4 + (size_t)m0 * HIDD;
    const __nv_bfloat16* Wh = (const __nv_bfloat16*)g_Whi4 + (size_t)z * HIDD * HIDD + (size_t)n0 * HIDD;
    const __nv_bfloat16* Wl = (const __nv_bfloat16*)g_Wlo4 + (size_t)z * HIDD * HIDD + (size_t)n0 * HIDD;
    const float* bias = (z == 0) ? bq : (z == 1) ? bk : bv;
    float* out = (z == 0) ? oq : (z == 1) ? ok : ov;

    const int lane = tid & 31;
    const int warp = tid >> 5;
    const int wm = warp >> 1;
    const int wn = warp & 1;
    const int qr = lane >> 2;
    const int qc = lane & 3;
    const int rA = wm * 32;
    const int cB = wn * 64;

    float acc[2][8][4];
#pragma unroll
    for (int mt = 0; mt < 2; mt++)
#pragma unroll
        for (int nt = 0; nt < 8; nt++)
#pragma unroll
            for (int e = 0; e < 4; e++) acc[mt][nt][e] = 0.0f;

    gemm_load_stage(gsm, Ah, Al, Wh, Wl, 0, tid);

    const int NIT = HIDD / 32;       // 32
    for (int it = 0; it < NIT; it++) {
        if (it + 1 < NIT) {
            gemm_load_stage(gsm + ((it + 1) & 1) * STGW, Ah, Al, Wh, Wl,
                            (it + 1) * 32, tid);
            cp_wait<1>();
        } else {
            cp_wait<0>();
        }
        __syncthreads();

        const unsigned* sAh = gsm + (it & 1) * STGW + PA_HI;
        const unsigned* sAl = gsm + (it & 1) * STGW + PA_LO;
        const unsigned* sBh = gsm + (it & 1) * STGW + PB_HI;
        const unsigned* sBl = gsm + (it & 1) * STGW + PB_LO;

#pragma unroll
        for (int s = 0; s < 2; s++) {
            const int kw0 = s * 8 + qc;
            unsigned a_hi[2][4], a_lo[2][4];
#pragma unroll
            for (int mt = 0; mt < 2; mt++) {
                int r0 = (rA + mt * 16 + qr) * GSTR;
                int r1 = r0 + 8 * GSTR;
                a_hi[mt][0] = sAh[r0 + kw0];
                a_hi[mt][1] = sAh[r1 + kw0];
                a_hi[mt][2] = sAh[r0 + kw0 + 4];
                a_hi[mt][3] = sAh[r1 + kw0 + 4];
                a_lo[mt][0] = sAl[r0 + kw0];
                a_lo[mt][1] = sAl[r1 + kw0];
                a_lo[mt][2] = sAl[r0 + kw0 + 4];
                a_lo[mt][3] = sAl[r1 + kw0 + 4];
            }
#pragma unroll
            for (int nt = 0; nt < 8; nt++) {
                int rb = (cB + nt * 8 + qr) * GSTR;
                unsigned b_hi0 = sBh[rb + kw0];
                unsigned b_hi1 = sBh[rb + kw0 + 4];
                unsigned b_lo0 = sBl[rb + kw0];
                unsigned b_lo1 = sBl[rb + kw0 + 4];
#pragma unroll
                for (int mt = 0; mt < 2; mt++) {
                    float* c = acc[mt][nt];
                    mma_bf16(c[0], c[1], c[2], c[3],
                             a_hi[mt][0], a_hi[mt][1], a_hi[mt][2], a_hi[mt][3],
                             b_hi0, b_hi1);
                    mma_bf16(c[0], c[1], c[2], c[3],
                             a_hi[mt][0], a_hi[mt][1], a_hi[mt][2], a_hi[mt][3],
                             b_lo0, b_lo1);
                    mma_bf16(c[0], c[1], c[2], c[3],
                             a_lo[mt][0], a_lo[mt][1], a_lo[mt][2], a_lo[mt][3],
                             b_hi0, b_hi1);
                }
            }
        }
        __syncthreads();
    }

    // epilogue: add bias, remap flat (m,col) -> (n,h,t,d)
#pragma unroll
    for (int mt = 0; mt < 2; mt++) {
#pragma unroll
        for (int nt = 0; nt < 8; nt++) {
#pragma unroll
            for (int half = 0; half < 2; half++) {
                int row = m0 + rA + mt * 16 + qr + half * 8;
                int nb  = row >> 12;
                int t   = row & (TT - 1);
                int col = n0 + cB + nt * 8 + qc * 2;
                int h = col >> 6;
                int d = col & 63;
                float* op = out + (((size_t)(nb * NHH + h)) * TT + t) * DD + d;
                op[0] = acc[mt][nt][half * 2 + 0] + bias[col];
                op[1] = acc[mt][nt][half * 2 + 1] + bias[col + 1];
            }
        }
    }
}

// ---------------- norm-based top-k selection per 64-token block -------------------
__global__ void select_kernel(const float* __restrict__ mask,
                              const float* __restrict__ bq)
{
    const int blk = blockIdx.x;
    const int h   = blockIdx.y;
    const int n   = blockIdx.z;
    const int i   = threadIdx.x;
    __shared__ float norms[64];
    __shared__ int flags[64];

    const int token = blk * 64 + i;
    const float* kr = g_k + (((size_t)(n * NHH + h)) * TT + token) * DD;
    const float* bqr = bq + h * DD;
    float s = 0.0f;
#pragma unroll
    for (int d = 0; d < DD; d++) { float vv = kr[d] + bqr[d]; s += vv * vv; }
    if (mask[n * TT + token] != 0.0f) s = 0.0f;
    norms[i] = s;
    __syncthreads();

    float mine = norms[i];
    int rank = 0;
    for (int j = 0; j < 64; j++) {
        float nj = norms[j];
        rank += (nj < mine) || (nj == mine && j < i);
    }
    int top = (rank >= 64 - TOPKK) ? 1 : 0;
    flags[i] = top;
    __syncthreads();

    int pos = 0;
    for (int j = 0; j < i; j++) pos += flags[j];
    if (top)
        g_gidx[((size_t)(n * NHH + h)) * (TT / 4) + blk * TOPKK + pos] = token;
    else
        g_lidx[((size_t)(n * NHH + h)) * (3 * TT / 4) + blk * 48 + (i - pos)] = token;
}

// ---------------- global pass: 64 queries x 48 gathered keys ----------------------
__global__ void attn_global_kernel(const float* __restrict__ mask)
{
    const int qb = blockIdx.x;
    const int h  = blockIdx.y;
    const int n  = blockIdx.z;
    const int tid = threadIdx.x;
    __shared__ float ks[48 * 64];
    __shared__ float vs[48 * 64];
    __shared__ float ms[48];
    __shared__ float sc[64 * 49];

    const size_t ho = (size_t)(n * NHH + h);
    const float* kb = g_k + ho * TT * DD;
    const float* vb = g_v + ho * TT * DD;
    const int* gix = g_gidx + ho * (TT / 4);

    for (int idx = tid; idx < 48 * 64; idx += 64) {
        int r = idx >> 6, c = idx & 63;
        int g = qb * 16 - 16 + r;
        float kvv = 0.0f, vvv = 0.0f;
        if (g >= 0 && g < TT / 4) {
            int src = gix[g];
            kvv = kb[(size_t)src * DD + c];
            vvv = vb[(size_t)src * DD + c];
            if (c == 0) ms[r] = mask[n * TT + src];
        } else {
            if (c == 0) ms[r] = NEGV;
        }
        ks[idx] = kvv; vs[idx] = vvv;
    }
    __syncthreads();

    const int qi = tid;
    const int tq = qb * 64 + qi;
    const float* qr = g_q + (ho * TT + tq) * DD;
    float qreg[64];
#pragma unroll
    for (int d = 0; d < 64; d++) qreg[d] = qr[d];

    float* row = sc + qi * 49;
    float mmax = -1e30f;
    for (int kk = 0; kk < 48; kk++) {
        float dot = 0.0f;
#pragma unroll
        for (int d = 0; d < 64; d++) dot = fmaf(qreg[d], ks[kk * 64 + d], dot);
        float s = dot * 0.125f + ms[kk];
        row[kk] = s;
        mmax = fmaxf(mmax, s);
    }
    float l = 0.0f;
    for (int kk = 0; kk < 48; kk++) {
        float p = __expf(row[kk] - mmax);
        row[kk] = p;
        l += p;
    }
    g_lseg[ho * TT + tq] = mmax + logf(l);
    float inv = 1.0f / l;
    float* ctxr = g_ctxg + (ho * TT + tq) * DD;
    for (int d0 = 0; d0 < 64; d0 += 32) {
        float acc[32];
#pragma unroll
        for (int dd = 0; dd < 32; dd++) acc[dd] = 0.0f;
        for (int kk = 0; kk < 48; kk++) {
            float w = row[kk];
#pragma unroll
            for (int dd = 0; dd < 32; dd++)
                acc[dd] = fmaf(w, vs[kk * 64 + d0 + dd], acc[dd]);
        }
#pragma unroll
        for (int dd = 0; dd < 32; dd++) ctxr[d0 + dd] = acc[dd] * inv;
    }
}

// ============== local pass: tf32 tensor-core flash + merge + output ===============
#define KC     112
#define NCHK   3
#define QSTRW  68
#define VSTRW  72
#define PSTRW  116
#define QS_OFF 0
#define KS_OFF (QS_OFF + 128*QSTRW)
#define VS_OFF (KS_OFF + KC*QSTRW)
#define PS_OFF (VS_OFF + KC*VSTRW)
#define MS_OFF (PS_OFF + 128*PSTRW)
#define LSMEM_WORDS (MS_OFF + KC)

__device__ __forceinline__ float to_tf32(float x)
{
    float r;
    asm("cvt.rna.tf32.f32 %0, %1;" : "=f"(r) : "f"(x));
    return r;
}

__device__ __forceinline__ void mma_tf32(float& d0, float& d1, float& d2, float& d3,
                                         float a0, float a1, float a2, float a3,
                                         float b0, float b1)
{
    asm volatile(
        "mma.sync.aligned.m16n8k8.row.col.f32.tf32.tf32.f32 "
        "{%0,%1,%2,%3}, {%4,%5,%6,%7}, {%8,%9}, {%0,%1,%2,%3};\n"
        : "+f"(d0), "+f"(d1), "+f"(d2), "+f"(d3)
        : "r"(__float_as_uint(a0)), "r"(__float_as_uint(a1)),
          "r"(__float_as_uint(a2)), "r"(__float_as_uint(a3)),
          "r"(__float_as_uint(b0)), "r"(__float_as_uint(b1)));
}

__global__ __launch_bounds__(256)
void attn_local_tc_kernel(const float* __restrict__ mask,
                          float* __restrict__ out)
{
    extern __shared__ float sm[];
    float* Qs = sm + QS_OFF;
    float* Ks = sm + KS_OFF;
    float* Vs = sm + VS_OFF;
    float* Ps = sm + PS_OFF;
    float* Ms = sm + MS_OFF;

    const int qb = blockIdx.x;
    const int h  = blockIdx.y;
    const int n  = blockIdx.z;
    const int tid = threadIdx.x;
    const int lane = tid & 31;
    const int warp = tid >> 5;
    const int qr = lane >> 2;
    const int qc = lane & 3;
    const int w16 = warp * 16;

    const size_t ho = (size_t)(n * NHH + h);
    const float* kb = g_k + ho * TT * DD;
    const float* vb = g_v + ho * TT * DD;
    const int* lix = g_lidx + ho * (3 * TT / 4);

#pragma unroll
    for (int i = 0; i < 8; i++) {
        int idx = tid + i * 256;
        int r = idx >> 4, c4 = idx & 15;
        const float4 qv = *(const float4*)(g_q + (ho * TT + qb * 128 + r) * DD + c4 * 4);
        float* dst = Qs + r * QSTRW + c4 * 4;
        dst[0] = to_tf32(qv.x); dst[1] = to_tf32(qv.y);
        dst[2] = to_tf32(qv.z); dst[3] = to_tf32(qv.w);
    }

    float m0 = -1e30f, m1 = -1e30f, l0 = 0.0f, l1 = 0.0f;
    float o[8][4];
#pragma unroll
    for (int nt = 0; nt < 8; nt++)
#pragma unroll
        for (int e = 0; e < 4; e++) o[nt][e] = 0.0f;

    for (int ch = 0; ch < NCHK; ch++) {
        __syncthreads();
        for (int idx = tid; idx < KC * 16; idx += 256) {
            int r = idx >> 4, c4 = idx & 15;
            int kk = ch * KC + r;
            float4 kv = make_float4(0.f, 0.f, 0.f, 0.f);
            float4 vv = make_float4(0.f, 0.f, 0.f, 0.f);
            float mval = -1e30f;
            if (kk < 288) {
                int g = qb * 96 - 96 + kk;
                if (g >= 0 && g < 3 * TT / 4) {
                    int src = lix[g];
                    kv = *(const float4*)(kb + (size_t)src * DD + c4 * 4);
                    vv = *(const float4*)(vb + (size_t)src * DD + c4 * 4);
                    mval = mask[n * TT + src];
                } else {
                    mval = NEGV;
                }
            } else if (kk == 288) {
                kv = *(const float4*)(kb + c4 * 4);
                vv = *(const float4*)(vb + c4 * 4);
                mval = 0.0f;
            }
            float* kd = Ks + r * QSTRW + c4 * 4;
            kd[0] = to_tf32(kv.x); kd[1] = to_tf32(kv.y);
            kd[2] = to_tf32(kv.z); kd[3] = to_tf32(kv.w);
            float* vd = Vs + r * VSTRW + c4 * 4;
            vd[0] = to_tf32(vv.x); vd[1] = to_tf32(vv.y);
            vd[2] = to_tf32(vv.z); vd[3] = to_tf32(vv.w);
            if (c4 == 0) Ms[r] = mval;
        }
        __syncthreads();

        float s[14][4];
#pragma unroll
        for (int nt = 0; nt < 14; nt++)
#pragma unroll
            for (int e = 0; e < 4; e++) s[nt][e] = 0.0f;

#pragma unroll
        for (int k8 = 0; k8 < 8; k8++) {
            const int kc0 = k8 * 8 + qc;
            float a0 = Qs[(w16 + qr) * QSTRW + kc0];
            float a1 = Qs[(w16 + qr + 8) * QSTRW + kc0];
            float a2 = Qs[(w16 + qr) * QSTRW + kc0 + 4];
            float a3 = Qs[(w16 + qr + 8) * QSTRW + kc0 + 4];
#pragma unroll
            for (int nt = 0; nt < 14; nt++) {
                float b0 = Ks[(nt * 8 + qr) * QSTRW + kc0];
                float b1 = Ks[(nt * 8 + qr) * QSTRW + kc0 + 4];
                mma_tf32(s[nt][0], s[nt][1], s[nt][2], s[nt][3],
                         a0, a1, a2, a3, b0, b1);
            }
        }

        float cmax0 = -1e30f, cmax1 = -1e30f;
#pragma unroll
        for (int nt = 0; nt < 14; nt++) {
            float mc0 = Ms[nt * 8 + 2 * qc];
            float mc1 = Ms[nt * 8 + 2 * qc + 1];
            s[nt][0] = s[nt][0] * 0.125f + mc0;
            s[nt][1] = s[nt][1] * 0.125f + mc1;
            s[nt][2] = s[nt][2] * 0.125f + mc0;
            s[nt][3] = s[nt][3] * 0.125f + mc1;
            cmax0 = fmaxf(cmax0, fmaxf(s[nt][0], s[nt][1]));
            cmax1 = fmaxf(cmax1, fmaxf(s[nt][2], s[nt][3]));
        }
        cmax0 = fmaxf(cmax0, __shfl_xor_sync(0xffffffffu, cmax0, 1));
        cmax0 = fmaxf(cmax0, __shfl_xor_sync(0xffffffffu, cmax0, 2));
        cmax1 = fmaxf(cmax1, __shfl_xor_sync(0xffffffffu, cmax1, 1));
        cmax1 = fmaxf(cmax1, __shfl_xor_sync(0xffffffffu, cmax1, 2));

        float mn0 = fmaxf(m0, cmax0);
        float mn1 = fmaxf(m1, cmax1);
        float corr0 = __expf(m0 - mn0);
        float corr1 = __expf(m1 - mn1);
        m0 = mn0; m1 = mn1;

        float rs0 = 0.0f, rs1 = 0.0f;
#pragma unroll
        for (int nt = 0; nt < 14; nt++) {
            float p0 = __expf(s[nt][0] - mn0);
            float p1 = __expf(s[nt][1] - mn0);
            float p2 = __expf(s[nt][2] - mn1);
            float p3 = __expf(s[nt][3] - mn1);
            rs0 += p0 + p1; rs1 += p2 + p3;
            float* pr0 = Ps + (w16 + qr) * PSTRW + nt * 8 + 2 * qc;
            float* pr1 = Ps + (w16 + qr + 8) * PSTRW + nt * 8 + 2 * qc;
            pr0[0] = to_tf32(p0); pr0[1] = to_tf32(p1);
            pr1[0] = to_tf32(p2); pr1[1] = to_tf32(p3);
        }
        rs0 += __shfl_xor_sync(0xffffffffu, rs0, 1);
        rs0 += __shfl_xor_sync(0xffffffffu, rs0, 2);
        rs1 += __shfl_xor_sync(0xffffffffu, rs1, 1);
        rs1 += __shfl_xor_sync(0xffffffffu, rs1, 2);
        l0 = l0 * corr0 + rs0;
        l1 = l1 * corr1 + rs1;

#pragma unroll
        for (int nt = 0; nt < 8; nt++) {
            o[nt][0] *= corr0; o[nt][1] *= corr0;
            o[nt][2] *= corr1; o[nt][3] *= corr1;
        }
        __syncwarp();

#pragma unroll
        for (int kt = 0; kt < 14; kt++) {
            const int kc0 = kt * 8 + qc;
            float a0 = Ps[(w16 + qr) * PSTRW + kc0];
            float a1 = Ps[(w16 + qr + 8) * PSTRW + kc0];
            float a2 = Ps[(w16 + qr) * PSTRW + kc0 + 4];
            float a3 = Ps[(w16 + qr + 8) * PSTRW + kc0 + 4];
#pragma unroll
            for (int nt = 0; nt < 8; nt++) {
                float b0 = Vs[(kt * 8 + qc) * VSTRW + nt * 8 + qr];
                float b1 = Vs[(kt * 8 + qc + 4) * VSTRW + nt * 8 + qr];
                mma_tf32(o[nt][0], o[nt][1], o[nt][2], o[nt][3],
                         a0, a1, a2, a3, b0, b1);
            }
        }
    }

    float lse0 = m0 + logf(l0);
    float lse1 = m1 + logf(l1);
    float inv0 = 1.0f / l0;
    float inv1 = 1.0f / l1;

    int row0 = qb * 128 + w16 + qr;
    int row1 = row0 + 8;
    float lg0 = g_lseg[ho * TT + row0];
    float lg1 = g_lseg[ho * TT + row1];
    float pm0 = 1.0f / (1.0f + __expf(lg0 - lse0));
    float pm1 = 1.0f / (1.0f + __expf(lg1 - lse1));

    const float* cg0 = g_ctxg + (ho * TT + row0) * DD;
    const float* cg1 = g_ctxg + (ho * TT + row1) * DD;
    float* op0 = out + ((size_t)n * TT + row0) * HIDD + h * DD;
    float* op1 = out + ((size_t)n * TT + row1) * HIDD + h * DD;

#pragma unroll
    for (int nt = 0; nt < 8; nt++) {
        int c0 = nt * 8 + 2 * qc;
#pragma unroll
        for (int e = 0; e < 2; e++) {
            float cl0 = o[nt][e] * inv0;
            float cv0 = cg0[c0 + e];
            op0[c0 + e] = cv0 + pm0 * (cl0 - cv0);
            float cl1 = o[nt][2 + e] * inv1;
            float cv1 = cg1[c0 + e];
            op1[c0 + e] = cv1 + pm1 * (cl1 - cv1);
        }
    }
}

// ---------------- BOS row ---------------------------------------------------------
__global__ void bos_kernel(const float* __restrict__ mask,
                           float* __restrict__ out)
{
    const int h = blockIdx.x;
    const int n = blockIdx.y;
    const int tid = threadIdx.x;
    __shared__ float sc[TT];
    __shared__ float qs[64];
    __shared__ float red[128];

    const size_t ho = (size_t)(n * NHH + h);
    const float* kb = g_k + ho * TT * DD;
    const float* vb = g_v + ho * TT * DD;
    if (tid < 64) qs[tid] = g_q[(ho * TT) * DD + tid];
    __syncthreads();

    float lmax = -1e30f;
    for (int t = tid; t < TT; t += 128) {
        const float* kr = kb + (size_t)t * DD;
        float dot = 0.0f;
#pragma unroll
        for (int d = 0; d < 64; d++) dot = fmaf(qs[d], kr[d], dot);
        float s = dot + mask[n * TT + t];
        sc[t] = s;
        lmax = fmaxf(lmax, s);
    }
    red[tid] = lmax;
    __syncthreads();
    for (int off = 64; off > 0; off >>= 1) {
        if (tid < off) red[tid] = fmaxf(red[tid], red[tid + off]);
        __syncthreads();
    }
    float mmax = red[0];
    float lsum = 0.0f;
    for (int t = tid; t < TT; t += 128) {
        float p = __expf(sc[t] - mmax);
        sc[t] = p;
        lsum += p;
    }
    __syncthreads();
    red[tid] = lsum;
    __syncthreads();
    for (int off = 64; off > 0; off >>= 1) {
        if (tid < off) red[tid] += red[tid + off];
        __syncthreads();
    }
    float inv = 1.0f / red[0];
    if (tid < 64) {
        int d = tid;
        float acc = 0.0f;
        for (int t = 0; t < TT; t++)
            acc = fmaf(sc[t], vb[(size_t)t * DD + d], acc);
        out[((size_t)n * TT) * HIDD + h * DD + d] = acc * inv;
    }
}

// ---------------- launch ----------------------------------------------------------
extern "C" void kernel_launch(void* const* d_in, const int* in_sizes, int n_in,
                              void* d_out, int out_size)
{
    (void)in_sizes; (void)n_in; (void)out_size;
    const float* hs   = (const float*)d_in[0];
    const float* mask = (const float*)d_in[1];
    const float* Wq   = (const float*)d_in[2];
    const float* bq   = (const float*)d_in[3];
    const float* Wk   = (const float*)d_in[4];
    const float* bk   = (const float*)d_in[5];
    const float* Wv   = (const float*)d_in[6];
    const float* bv   = (const float*)d_in[7];
    float* out = (float*)d_out;

    float *qp, *kp, *vp;
    cudaGetSymbolAddress((void**)&qp, g_q);
    cudaGetSymbolAddress((void**)&kp, g_k);
    cudaGetSymbolAddress((void**)&vp, g_v);
    uint2 *ahp, *alp, *whp, *wlp;
    cudaGetSymbolAddress((void**)&ahp, g_Ahi4);
    cudaGetSymbolAddress((void**)&alp, g_Alo4);
    cudaGetSymbolAddress((void**)&whp, g_Whi4);
    cudaGetSymbolAddress((void**)&wlp, g_Wlo4);

    // split-conversion of activations and weights (uint2 = 4 bf16 elements)
    {
        int n4a = NB * TT * HIDD / 4;          // 2,097,152
        cvt_split_kernel<<<(n4a + 255) / 256, 256>>>(hs, ahp, alp, n4a);
        int n4w = HIDD * HIDD / 4;             // 262,144
        size_t wq4 = (size_t)HIDD * HIDD / 4;  // uint2 elements per W
        cvt_split_kernel<<<(n4w + 255) / 256, 256>>>(Wq, whp, wlp, n4w);
        cvt_split_kernel<<<(n4w + 255) / 256, 256>>>(Wk, whp + wq4, wlp + wq4, n4w);
        cvt_split_kernel<<<(n4w + 255) / 256, 256>>>(Wv, whp + 2 * wq4, wlp + 2 * wq4, n4w);
    }

    // fused QKV projection
    {
        size_t gsmem = (size_t)(2 * STGW) * sizeof(unsigned);   // 80 KB
        cudaFuncSetAttribute(gemm_qkv_kernel,
                             cudaFuncAttributeMaxDynamicSharedMemorySize, (int)gsmem);
        dim3 ggrid(HIDD / 128, (NB * TT) / 128, 3);
        gemm_qkv_kernel<<<ggrid, 256, gsmem>>>(bq, bk, bv, qp, kp, vp);
    }

    select_kernel<<<dim3(TT / 64, NHH, NB), 64>>>(mask, bq);

    attn_global_kernel<<<dim3(TT / 64, NHH, NB), 64>>>(mask);

    size_t lsmem = (size_t)LSMEM_WORDS * sizeof(float);
    cudaFuncSetAttribute(attn_local_tc_kernel,
                         cudaFuncAttributeMaxDynamicSharedMemorySize, (int)lsmem);
    attn_local_tc_kernel<<<dim3(TT / 128, NHH, NB), 256, lsmem>>>(mask, out);

    bos_kernel<<<dim3(NHH, NB), 128>>>(mask, out);
}

// round 8
// speedup vs baseline: 2.4705x; 1.0461x over previous
#include <cuda_runtime.h>
#include <cuda_bf16.h>
#include <math.h>

#define NB   2
#define TT   4096
#define HIDD 1024
#define NHH  16
#define DD   64
#define TOPKK 16
#define NEGV (-10000.0f)

// ---------------- device scratch ----------------
__device__ float g_q[(size_t)NB*NHH*TT*DD];
__device__ float g_k[(size_t)NB*NHH*TT*DD];
__device__ float g_v[(size_t)NB*NHH*TT*DD];
__device__ float g_ctxg[(size_t)NB*NHH*TT*DD];
__device__ float g_lseg[(size_t)NB*NHH*TT];
__device__ int   g_gidx[(size_t)NB*NHH*(TT/4)];
__device__ int   g_lidx[(size_t)NB*NHH*(3*TT/4)];
// split-bf16 planes — uint4-typed so the base is 16-byte aligned
__device__ uint4 g_Ahi4[(size_t)NB*TT*HIDD/8];
__device__ uint4 g_Alo4[(size_t)NB*TT*HIDD/8];
__device__ uint4 g_Whi4[(size_t)3*HIDD*HIDD/8];
__device__ uint4 g_Wlo4[(size_t)3*HIDD*HIDD/8];

// ---------------- helpers ----------------
__device__ __forceinline__ unsigned short f2bf(float x)
{
    unsigned u = __float_as_uint(x);
    u += 0x7FFFu + ((u >> 16) & 1u);
    return (unsigned short)(u >> 16);
}
__device__ __forceinline__ float bf2f(unsigned short h)
{
    return __uint_as_float(((unsigned)h) << 16);
}

__device__ __forceinline__ void mma_bf16(float& d0, float& d1, float& d2, float& d3,
                                         unsigned a0, unsigned a1, unsigned a2, unsigned a3,
                                         unsigned b0, unsigned b1)
{
    asm volatile(
        "mma.sync.aligned.m16n8k16.row.col.f32.bf16.bf16.f32 "
        "{%0,%1,%2,%3}, {%4,%5,%6,%7}, {%8,%9}, {%0,%1,%2,%3};\n"
        : "+f"(d0), "+f"(d1), "+f"(d2), "+f"(d3)
        : "r"(a0), "r"(a1), "r"(a2), "r"(a3), "r"(b0), "r"(b1));
}

__device__ __forceinline__ void ldsm4(unsigned& r0, unsigned& r1,
                                      unsigned& r2, unsigned& r3, unsigned saddr)
{
    asm volatile("ldmatrix.sync.aligned.m8n8.x4.shared.b16 {%0,%1,%2,%3}, [%4];"
                 : "=r"(r0), "=r"(r1), "=r"(r2), "=r"(r3) : "r"(saddr));
}

__device__ __forceinline__ void cp16(void* smem_dst, const void* gsrc)
{
    unsigned saddr = (unsigned)__cvta_generic_to_shared(smem_dst);
    asm volatile("cp.async.ca.shared.global [%0], [%1], 16;\n"
                 :: "r"(saddr), "l"(gsrc));
}
__device__ __forceinline__ void cp_commit()
{
    asm volatile("cp.async.commit_group;\n" ::: "memory");
}
template <int N> __device__ __forceinline__ void cp_wait()
{
    asm volatile("cp.async.wait_group %0;\n" :: "n"(N) : "memory");
}

// ---------------- split conversion: fp32 -> hi/lo bf16 planes ---------------------
__global__ void cvt_split_kernel(const float* __restrict__ in,
                                 uint2* __restrict__ hi,
                                 uint2* __restrict__ lo, int n4)
{
    int i = blockIdx.x * blockDim.x + threadIdx.x;
    if (i >= n4) return;
    float4 v = ((const float4*)in)[i];
    unsigned short h0 = f2bf(v.x), h1 = f2bf(v.y), h2 = f2bf(v.z), h3 = f2bf(v.w);
    unsigned short l0 = f2bf(v.x - bf2f(h0)), l1 = f2bf(v.y - bf2f(h1));
    unsigned short l2 = f2bf(v.z - bf2f(h2)), l3 = f2bf(v.w - bf2f(h3));
    hi[i] = make_uint2((unsigned)h0 | ((unsigned)h1 << 16),
                       (unsigned)h2 | ((unsigned)h3 << 16));
    lo[i] = make_uint2((unsigned)l0 | ((unsigned)l1 << 16),
                       (unsigned)l2 | ((unsigned)l3 << 16));
}

// all 3 weights in one launch (blockIdx.y selects the matrix)
__global__ void cvt_split_w_kernel(const float* __restrict__ Wq,
                                   const float* __restrict__ Wk,
                                   const float* __restrict__ Wv,
                                   uint2* __restrict__ hi,
                                   uint2* __restrict__ lo, int n4)
{
    int i = blockIdx.x * blockDim.x + threadIdx.x;
    if (i >= n4) return;
    int w = blockIdx.y;
    const float* in = (w == 0) ? Wq : (w == 1) ? Wk : Wv;
    float4 v = ((const float4*)in)[i];
    unsigned short h0 = f2bf(v.x), h1 = f2bf(v.y), h2 = f2bf(v.z), h3 = f2bf(v.w);
    unsigned short l0 = f2bf(v.x - bf2f(h0)), l1 = f2bf(v.y - bf2f(h1));
    unsigned short l2 = f2bf(v.z - bf2f(h2)), l3 = f2bf(v.w - bf2f(h3));
    size_t o = (size_t)w * n4 + i;
    hi[o] = make_uint2((unsigned)h0 | ((unsigned)h1 << 16),
                       (unsigned)h2 | ((unsigned)h3 << 16));
    lo[o] = make_uint2((unsigned)l0 | ((unsigned)l1 << 16),
                       (unsigned)l2 | ((unsigned)l3 << 16));
}

// ============= fused QKV GEMM: out_z = X @ Wz^T + bz  (split-bf16, cp.async) ======
// Tiles 128x128x32, 256 threads (8 warps 4m x 2n), double-buffered smem,
// ldmatrix.x4 fragment loads (row stride 80B: 16B-aligned, LDSM conflict-free).
#define GSTR 20                       /* row stride in words (80 bytes) */
#define PLW  (128 * GSTR)             /* words per plane = 2560 */
#define PA_HI 0
#define PA_LO (1 * PLW)
#define PB_HI (2 * PLW)
#define PB_LO (3 * PLW)
#define STGW  (4 * PLW)               /* words per stage = 10240 (40KB) */

__device__ __forceinline__ void gemm_load_stage(unsigned* st,
                                                const __nv_bfloat16* Ah,
                                                const __nv_bfloat16* Al,
                                                const __nv_bfloat16* Wh,
                                                const __nv_bfloat16* Wl,
                                                int kofs, int tid)
{
#pragma unroll
    for (int i = 0; i < 2; i++) {
        int c = tid + i * 256;        // 0..511
        int row = c >> 2;
        int cw = c & 3;
        size_t go = (size_t)row * HIDD + kofs + cw * 8;
        unsigned* sp = st + row * GSTR + cw * 4;
        cp16(sp + PA_HI, Ah + go);
        cp16(sp + PA_LO, Al + go);
        cp16(sp + PB_HI, Wh + go);
        cp16(sp + PB_LO, Wl + go);
    }
    cp_commit();
}

__global__ __launch_bounds__(256, 2)
void gemm_qkv_kernel(const float* __restrict__ bq,
                     const float* __restrict__ bk,
                     const float* __restrict__ bv,
                     float* __restrict__ oq,
                     float* __restrict__ ok,
                     float* __restrict__ ov)
{
    extern __shared__ unsigned gsm[];

    const int tid = threadIdx.x;
    const int m0 = blockIdx.y * 128;
    const int n0 = blockIdx.x * 128;
    const int z  = blockIdx.z;

    const __nv_bfloat16* Ah = (const __nv_bfloat16*)g_Ahi4 + (size_t)m0 * HIDD;
    const __nv_bfloat16* Al = (const __nv_bfloat16*)g_Alo4 + (size_t)m0 * HIDD;
    const __nv_bfloat16* Wh = (const __nv_bfloat16*)g_Whi4 + (size_t)z * HIDD * HIDD + (size_t)n0 * HIDD;
    const __nv_bfloat16* Wl = (const __nv_bfloat16*)g_Wlo4 + (size_t)z * HIDD * HIDD + (size_t)n0 * HIDD;
    const float* bias = (z == 0) ? bq : (z == 1) ? bk : bv;
    float* out = (z == 0) ? oq : (z == 1) ? ok : ov;

    const int lane = tid & 31;
    const int warp = tid >> 5;
    const int wm = warp >> 1;
    const int wn = warp & 1;
    const int qr = lane >> 2;
    const int qc = lane & 3;
    const int rA = wm * 32;
    const int cB = wn * 64;

    // ldmatrix per-thread address components (bytes)
    const unsigned smem_base = (unsigned)__cvta_generic_to_shared(gsm);
    const int a_row = rA + (lane & 7) + ((lane >> 3) & 1) * 8;   // + mt*16
    const unsigned a_k = ((lane >> 4) & 1) * 16;                 // + s*32
    const int b_row = cB + (lane & 7) + ((lane >> 4) & 1) * 8;   // + p*16
    const unsigned b_k = ((lane >> 3) & 1) * 16;                 // + s*32

    float acc[2][8][4];
#pragma unroll
    for (int mt = 0; mt < 2; mt++)
#pragma unroll
        for (int nt = 0; nt < 8; nt++)
#pragma unroll
            for (int e = 0; e < 4; e++) acc[mt][nt][e] = 0.0f;

    gemm_load_stage(gsm, Ah, Al, Wh, Wl, 0, tid);

    const int NIT = HIDD / 32;       // 32
    for (int it = 0; it < NIT; it++) {
        if (it + 1 < NIT) {
            gemm_load_stage(gsm + ((it + 1) & 1) * STGW, Ah, Al, Wh, Wl,
                            (it + 1) * 32, tid);
            cp_wait<1>();
        } else {
            cp_wait<0>();
        }
        __syncthreads();

        const unsigned sb = smem_base + ((it & 1) * STGW) * 4;   // stage base (bytes)

#pragma unroll
        for (int s = 0; s < 2; s++) {
            // A fragments: 2 planes x 2 mt ldmatrix.x4
            unsigned a_hi[2][4], a_lo[2][4];
#pragma unroll
            for (int mt = 0; mt < 2; mt++) {
                unsigned ao = (unsigned)(a_row + mt * 16) * 80 + s * 32 + a_k;
                ldsm4(a_hi[mt][0], a_hi[mt][1], a_hi[mt][2], a_hi[mt][3],
                      sb + PA_HI * 4 + ao);
                ldsm4(a_lo[mt][0], a_lo[mt][1], a_lo[mt][2], a_lo[mt][3],
                      sb + PA_LO * 4 + ao);
            }
            // B fragments in pairs of two n-tiles, interleaved with MMAs
#pragma unroll
            for (int p = 0; p < 4; p++) {
                unsigned bo = (unsigned)(b_row + p * 16) * 80 + s * 32 + b_k;
                unsigned bh0a, bh1a, bh0b, bh1b, bl0a, bl1a, bl0b, bl1b;
                ldsm4(bh0a, bh1a, bh0b, bh1b, sb + PB_HI * 4 + bo);
                ldsm4(bl0a, bl1a, bl0b, bl1b, sb + PB_LO * 4 + bo);
#pragma unroll
                for (int mt = 0; mt < 2; mt++) {
                    float* c0 = acc[mt][2 * p];
                    mma_bf16(c0[0], c0[1], c0[2], c0[3],
                             a_hi[mt][0], a_hi[mt][1], a_hi[mt][2], a_hi[mt][3],
                             bh0a, bh1a);
                    mma_bf16(c0[0], c0[1], c0[2], c0[3],
                             a_hi[mt][0], a_hi[mt][1], a_hi[mt][2], a_hi[mt][3],
                             bl0a, bl1a);
                    mma_bf16(c0[0], c0[1], c0[2], c0[3],
                             a_lo[mt][0], a_lo[mt][1], a_lo[mt][2], a_lo[mt][3],
                             bh0a, bh1a);
                    float* c1 = acc[mt][2 * p + 1];
                    mma_bf16(c1[0], c1[1], c1[2], c1[3],
                             a_hi[mt][0], a_hi[mt][1], a_hi[mt][2], a_hi[mt][3],
                             bh0b, bh1b);
                    mma_bf16(c1[0], c1[1], c1[2], c1[3],
                             a_hi[mt][0], a_hi[mt][1], a_hi[mt][2], a_hi[mt][3],
                             bl0b, bl1b);
                    mma_bf16(c1[0], c1[1], c1[2], c1[3],
                             a_lo[mt][0], a_lo[mt][1], a_lo[mt][2], a_lo[mt][3],
                             bh0b, bh1b);
                }
            }
        }
        __syncthreads();
    }

    // epilogue: add bias, remap flat (m,col) -> (n,h,t,d)
#pragma unroll
    for (int mt = 0; mt < 2; mt++) {
#pragma unroll
        for (int nt = 0; nt < 8; nt++) {
#pragma unroll
            for (int half = 0; half < 2; half++) {
                int row = m0 + rA + mt * 16 + qr + half * 8;
                int nb  = row >> 12;
                int t   = row & (TT - 1);
                int col = n0 + cB + nt * 8 + qc * 2;
                int h = col >> 6;
                int d = col & 63;
                float* op = out + (((size_t)(nb * NHH + h)) * TT + t) * DD + d;
                op[0] = acc[mt][nt][half * 2 + 0] + bias[col];
                op[1] = acc[mt][nt][half * 2 + 1] + bias[col + 1];
            }
        }
    }
}

// ---------------- norm-based top-k selection per 64-token block -------------------
__global__ void select_kernel(const float* __restrict__ mask,
                              const float* __restrict__ bq)
{
    const int blk = blockIdx.x;
    const int h   = blockIdx.y;
    const int n   = blockIdx.z;
    const int i   = threadIdx.x;
    __shared__ float norms[64];
    __shared__ int flags[64];

    const int token = blk * 64 + i;
    const float* kr = g_k + (((size_t)(n * NHH + h)) * TT + token) * DD;
    const float* bqr = bq + h * DD;
    float s = 0.0f;
#pragma unroll
    for (int d = 0; d < DD; d++) { float vv = kr[d] + bqr[d]; s += vv * vv; }
    if (mask[n * TT + token] != 0.0f) s = 0.0f;
    norms[i] = s;
    __syncthreads();

    float mine = norms[i];
    int rank = 0;
    for (int j = 0; j < 64; j++) {
        float nj = norms[j];
        rank += (nj < mine) || (nj == mine && j < i);
    }
    int top = (rank >= 64 - TOPKK) ? 1 : 0;
    flags[i] = top;
    __syncthreads();

    int pos = 0;
    for (int j = 0; j < i; j++) pos += flags[j];
    if (top)
        g_gidx[((size_t)(n * NHH + h)) * (TT / 4) + blk * TOPKK + pos] = token;
    else
        g_lidx[((size_t)(n * NHH + h)) * (3 * TT / 4) + blk * 48 + (i - pos)] = token;
}

// ---------------- global pass: 64 queries x 48 gathered keys ----------------------
__global__ void attn_global_kernel(const float* __restrict__ mask)
{
    const int qb = blockIdx.x;
    const int h  = blockIdx.y;
    const int n  = blockIdx.z;
    const int tid = threadIdx.x;
    __shared__ float ks[48 * 64];
    __shared__ float vs[48 * 64];
    __shared__ float ms[48];
    __shared__ float sc[64 * 49];

    const size_t ho = (size_t)(n * NHH + h);
    const float* kb = g_k + ho * TT * DD;
    const float* vb = g_v + ho * TT * DD;
    const int* gix = g_gidx + ho * (TT / 4);

    for (int idx = tid; idx < 48 * 64; idx += 64) {
        int r = idx >> 6, c = idx & 63;
        int g = qb * 16 - 16 + r;
        float kvv = 0.0f, vvv = 0.0f;
        if (g >= 0 && g < TT / 4) {
            int src = gix[g];
            kvv = kb[(size_t)src * DD + c];
            vvv = vb[(size_t)src * DD + c];
            if (c == 0) ms[r] = mask[n * TT + src];
        } else {
            if (c == 0) ms[r] = NEGV;
        }
        ks[idx] = kvv; vs[idx] = vvv;
    }
    __syncthreads();

    const int qi = tid;
    const int tq = qb * 64 + qi;
    const float* qr = g_q + (ho * TT + tq) * DD;
    float qreg[64];
#pragma unroll
    for (int d = 0; d < 64; d++) qreg[d] = qr[d];

    float* row = sc + qi * 49;
    float mmax = -1e30f;
    for (int kk = 0; kk < 48; kk++) {
        float dot = 0.0f;
#pragma unroll
        for (int d = 0; d < 64; d++) dot = fmaf(qreg[d], ks[kk * 64 + d], dot);
        float s = dot * 0.125f + ms[kk];
        row[kk] = s;
        mmax = fmaxf(mmax, s);
    }
    float l = 0.0f;
    for (int kk = 0; kk < 48; kk++) {
        float p = __expf(row[kk] - mmax);
        row[kk] = p;
        l += p;
    }
    g_lseg[ho * TT + tq] = mmax + logf(l);
    float inv = 1.0f / l;
    float* ctxr = g_ctxg + (ho * TT + tq) * DD;
    for (int d0 = 0; d0 < 64; d0 += 32) {
        float acc[32];
#pragma unroll
        for (int dd = 0; dd < 32; dd++) acc[dd] = 0.0f;
        for (int kk = 0; kk < 48; kk++) {
            float w = row[kk];
#pragma unroll
            for (int dd = 0; dd < 32; dd++)
                acc[dd] = fmaf(w, vs[kk * 64 + d0 + dd], acc[dd]);
        }
#pragma unroll
        for (int dd = 0; dd < 32; dd++) ctxr[d0 + dd] = acc[dd] * inv;
    }
}

// ============== local pass: tf32 tensor-core flash + merge + output ===============
#define KC     112
#define NCHK   3
#define QSTRW  68
#define VSTRW  72
#define PSTRW  116
#define QS_OFF 0
#define KS_OFF (QS_OFF + 128*QSTRW)
#define VS_OFF (KS_OFF + KC*QSTRW)
#define PS_OFF (VS_OFF + KC*VSTRW)
#define MS_OFF (PS_OFF + 128*PSTRW)
#define LSMEM_WORDS (MS_OFF + KC)

__device__ __forceinline__ float to_tf32(float x)
{
    float r;
    asm("cvt.rna.tf32.f32 %0, %1;" : "=f"(r) : "f"(x));
    return r;
}

__device__ __forceinline__ void mma_tf32(float& d0, float& d1, float& d2, float& d3,
                                         float a0, float a1, float a2, float a3,
                                         float b0, float b1)
{
    asm volatile(
        "mma.sync.aligned.m16n8k8.row.col.f32.tf32.tf32.f32 "
        "{%0,%1,%2,%3}, {%4,%5,%6,%7}, {%8,%9}, {%0,%1,%2,%3};\n"
        : "+f"(d0), "+f"(d1), "+f"(d2), "+f"(d3)
        : "r"(__float_as_uint(a0)), "r"(__float_as_uint(a1)),
          "r"(__float_as_uint(a2)), "r"(__float_as_uint(a3)),
          "r"(__float_as_uint(b0)), "r"(__float_as_uint(b1)));
}

__global__ __launch_bounds__(256)
void attn_local_tc_kernel(const float* __restrict__ mask,
                          float* __restrict__ out)
{
    extern __shared__ float sm[];
    float* Qs = sm + QS_OFF;
    float* Ks = sm + KS_OFF;
    float* Vs = sm + VS_OFF;
    float* Ps = sm + PS_OFF;
    float* Ms = sm + MS_OFF;

    const int qb = blockIdx.x;
    const int h  = blockIdx.y;
    const int n  = blockIdx.z;
    const int tid = threadIdx.x;
    const int lane = tid & 31;
    const int warp = tid >> 5;
    const int qr = lane >> 2;
    const int qc = lane & 3;
    const int w16 = warp * 16;

    const size_t ho = (size_t)(n * NHH + h);
    const float* kb = g_k + ho * TT * DD;
    const float* vb = g_v + ho * TT * DD;
    const int* lix = g_lidx + ho * (3 * TT / 4);

#pragma unroll
    for (int i = 0; i < 8; i++) {
        int idx = tid + i * 256;
        int r = idx >> 4, c4 = idx & 15;
        const float4 qv = *(const float4*)(g_q + (ho * TT + qb * 128 + r) * DD + c4 * 4);
        float* dst = Qs + r * QSTRW + c4 * 4;
        dst[0] = to_tf32(qv.x); dst[1] = to_tf32(qv.y);
        dst[2] = to_tf32(qv.z); dst[3] = to_tf32(qv.w);
    }

    float m0 = -1e30f, m1 = -1e30f, l0 = 0.0f, l1 = 0.0f;
    float o[8][4];
#pragma unroll
    for (int nt = 0; nt < 8; nt++)
#pragma unroll
        for (int e = 0; e < 4; e++) o[nt][e] = 0.0f;

    for (int ch = 0; ch < NCHK; ch++) {
        __syncthreads();
        for (int idx = tid; idx < KC * 16; idx += 256) {
            int r = idx >> 4, c4 = idx & 15;
            int kk = ch * KC + r;
            float4 kv = make_float4(0.f, 0.f, 0.f, 0.f);
            float4 vv = make_float4(0.f, 0.f, 0.f, 0.f);
            float mval = -1e30f;
            if (kk < 288) {
                int g = qb * 96 - 96 + kk;
                if (g >= 0 && g < 3 * TT / 4) {
                    int src = lix[g];
                    kv = *(const float4*)(kb + (size_t)src * DD + c4 * 4);
                    vv = *(const float4*)(vb + (size_t)src * DD + c4 * 4);
                    mval = mask[n * TT + src];
                } else {
                    mval = NEGV;
                }
            } else if (kk == 288) {
                kv = *(const float4*)(kb + c4 * 4);
                vv = *(const float4*)(vb + c4 * 4);
                mval = 0.0f;
            }
            float* kd = Ks + r * QSTRW + c4 * 4;
            kd[0] = to_tf32(kv.x); kd[1] = to_tf32(kv.y);
            kd[2] = to_tf32(kv.z); kd[3] = to_tf32(kv.w);
            float* vd = Vs + r * VSTRW + c4 * 4;
            vd[0] = to_tf32(vv.x); vd[1] = to_tf32(vv.y);
            vd[2] = to_tf32(vv.z); vd[3] = to_tf32(vv.w);
            if (c4 == 0) Ms[r] = mval;
        }
        __syncthreads();

        float s[14][4];
#pragma unroll
        for (int nt = 0; nt < 14; nt++)
#pragma unroll
            for (int e = 0; e < 4; e++) s[nt][e] = 0.0f;

#pragma unroll
        for (int k8 = 0; k8 < 8; k8++) {
            const int kc0 = k8 * 8 + qc;
            float a0 = Qs[(w16 + qr) * QSTRW + kc0];
            float a1 = Qs[(w16 + qr + 8) * QSTRW + kc0];
            float a2 = Qs[(w16 + qr) * QSTRW + kc0 + 4];
            float a3 = Qs[(w16 + qr + 8) * QSTRW + kc0 + 4];
#pragma unroll
            for (int nt = 0; nt < 14; nt++) {
                float b0 = Ks[(nt * 8 + qr) * QSTRW + kc0];
                float b1 = Ks[(nt * 8 + qr) * QSTRW + kc0 + 4];
                mma_tf32(s[nt][0], s[nt][1], s[nt][2], s[nt][3],
                         a0, a1, a2, a3, b0, b1);
            }
        }

        float cmax0 = -1e30f, cmax1 = -1e30f;
#pragma unroll
        for (int nt = 0; nt < 14; nt++) {
            float mc0 = Ms[nt * 8 + 2 * qc];
            float mc1 = Ms[nt * 8 + 2 * qc + 1];
            s[nt][0] = s[nt][0] * 0.125f + mc0;
            s[nt][1] = s[nt][1] * 0.125f + mc1;
            s[nt][2] = s[nt][2] * 0.125f + mc0;
            s[nt][3] = s[nt][3] * 0.125f + mc1;
            cmax0 = fmaxf(cmax0, fmaxf(s[nt][0], s[nt][1]));
            cmax1 = fmaxf(cmax1, fmaxf(s[nt][2], s[nt][3]));
        }
        cmax0 = fmaxf(cmax0, __shfl_xor_sync(0xffffffffu, cmax0, 1));
        cmax0 = fmaxf(cmax0, __shfl_xor_sync(0xffffffffu, cmax0, 2));
        cmax1 = fmaxf(cmax1, __shfl_xor_sync(0xffffffffu, cmax1, 1));
        cmax1 = fmaxf(cmax1, __shfl_xor_sync(0xffffffffu, cmax1, 2));

        float mn0 = fmaxf(m0, cmax0);
        float mn1 = fmaxf(m1, cmax1);
        float corr0 = __expf(m0 - mn0);
        float corr1 = __expf(m1 - mn1);
        m0 = mn0; m1 = mn1;

        float rs0 = 0.0f, rs1 = 0.0f;
#pragma unroll
        for (int nt = 0; nt < 14; nt++) {
            float p0 = __expf(s[nt][0] - mn0);
            float p1 = __expf(s[nt][1] - mn0);
            float p2 = __expf(s[nt][2] - mn1);
            float p3 = __expf(s[nt][3] - mn1);
            rs0 += p0 + p1; rs1 += p2 + p3;
            float* pr0 = Ps + (w16 + qr) * PSTRW + nt * 8 + 2 * qc;
            float* pr1 = Ps + (w16 + qr + 8) * PSTRW + nt * 8 + 2 * qc;
            pr0[0] = to_tf32(p0); pr0[1] = to_tf32(p1);
            pr1[0] = to_tf32(p2); pr1[1] = to_tf32(p3);
        }
        rs0 += __shfl_xor_sync(0xffffffffu, rs0, 1);
        rs0 += __shfl_xor_sync(0xffffffffu, rs0, 2);
        rs1 += __shfl_xor_sync(0xffffffffu, rs1, 1);
        rs1 += __shfl_xor_sync(0xffffffffu, rs1, 2);
        l0 = l0 * corr0 + rs0;
        l1 = l1 * corr1 + rs1;

#pragma unroll
        for (int nt = 0; nt < 8; nt++) {
            o[nt][0] *= corr0; o[nt][1] *= corr0;
            o[nt][2] *= corr1; o[nt][3] *= corr1;
        }
        __syncwarp();

#pragma unroll
        for (int kt = 0; kt < 14; kt++) {
            const int kc0 = kt * 8 + qc;
            float a0 = Ps[(w16 + qr) * PSTRW + kc0];
            float a1 = Ps[(w16 + qr + 8) * PSTRW + kc0];
            float a2 = Ps[(w16 + qr) * PSTRW + kc0 + 4];
            float a3 = Ps[(w16 + qr + 8) * PSTRW + kc0 + 4];
#pragma unroll
            for (int nt = 0; nt < 8; nt++) {
                float b0 = Vs[(kt * 8 + qc) * VSTRW + nt * 8 + qr];
                float b1 = Vs[(kt * 8 + qc + 4) * VSTRW + nt * 8 + qr];
                mma_tf32(o[nt][0], o[nt][1], o[nt][2], o[nt][3],
                         a0, a1, a2, a3, b0, b1);
            }
        }
    }

    float lse0 = m0 + logf(l0);
    float lse1 = m1 + logf(l1);
    float inv0 = 1.0f / l0;
    float inv1 = 1.0f / l1;

    int row0 = qb * 128 + w16 + qr;
    int row1 = row0 + 8;
    float lg0 = g_lseg[ho * TT + row0];
    float lg1 = g_lseg[ho * TT + row1];
    float pm0 = 1.0f / (1.0f + __expf(lg0 - lse0));
    float pm1 = 1.0f / (1.0f + __expf(lg1 - lse1));

    const float* cg0 = g_ctxg + (ho * TT + row0) * DD;
    const float* cg1 = g_ctxg + (ho * TT + row1) * DD;
    float* op0 = out + ((size_t)n * TT + row0) * HIDD + h * DD;
    float* op1 = out + ((size_t)n * TT + row1) * HIDD + h * DD;

#pragma unroll
    for (int nt = 0; nt < 8; nt++) {
        int c0 = nt * 8 + 2 * qc;
#pragma unroll
        for (int e = 0; e < 2; e++) {
            float cl0 = o[nt][e] * inv0;
            float cv0 = cg0[c0 + e];
            op0[c0 + e] = cv0 + pm0 * (cl0 - cv0);
            float cl1 = o[nt][2 + e] * inv1;
            float cv1 = cg1[c0 + e];
            op1[c0 + e] = cv1 + pm1 * (cl1 - cv1);
        }
    }
}

// ---------------- BOS row ---------------------------------------------------------
__global__ void bos_kernel(const float* __restrict__ mask,
                           float* __restrict__ out)
{
    const int h = blockIdx.x;
    const int n = blockIdx.y;
    const int tid = threadIdx.x;
    __shared__ float sc[TT];
    __shared__ float qs[64];
    __shared__ float red[128];

    const size_t ho = (size_t)(n * NHH + h);
    const float* kb = g_k + ho * TT * DD;
    const float* vb = g_v + ho * TT * DD;
    if (tid < 64) qs[tid] = g_q[(ho * TT) * DD + tid];
    __syncthreads();

    float lmax = -1e30f;
    for (int t = tid; t < TT; t += 128) {
        const float* kr = kb + (size_t)t * DD;
        float dot = 0.0f;
#pragma unroll
        for (int d = 0; d < 64; d++) dot = fmaf(qs[d], kr[d], dot);
        float s = dot + mask[n * TT + t];
        sc[t] = s;
        lmax = fmaxf(lmax, s);
    }
    red[tid] = lmax;
    __syncthreads();
    for (int off = 64; off > 0; off >>= 1) {
        if (tid < off) red[tid] = fmaxf(red[tid], red[tid + off]);
        __syncthreads();
    }
    float mmax = red[0];
    float lsum = 0.0f;
    for (int t = tid; t < TT; t += 128) {
        float p = __expf(sc[t] - mmax);
        sc[t] = p;
        lsum += p;
    }
    __syncthreads();
    red[tid] = lsum;
    __syncthreads();
    for (int off = 64; off > 0; off >>= 1) {
        if (tid < off) red[tid] += red[tid + off];
        __syncthreads();
    }
    float inv = 1.0f / red[0];
    if (tid < 64) {
        int d = tid;
        float acc = 0.0f;
        for (int t = 0; t < TT; t++)
            acc = fmaf(sc[t], vb[(size_t)t * DD + d], acc);
        out[((size_t)n * TT) * HIDD + h * DD + d] = acc * inv;
    }
}

// ---------------- launch ----------------------------------------------------------
extern "C" void kernel_launch(void* const* d_in, const int* in_sizes, int n_in,
                              void* d_out, int out_size)
{
    (void)in_sizes; (void)n_in; (void)out_size;
    const float* hs   = (const float*)d_in[0];
    const float* mask = (const float*)d_in[1];
    const float* Wq   = (const float*)d_in[2];
    const float* bq   = (const float*)d_in[3];
    const float* Wk   = (const float*)d_in[4];
    const float* bk   = (const float*)d_in[5];
    const float* Wv   = (const float*)d_in[6];
    const float* bv   = (const float*)d_in[7];
    float* out = (float*)d_out;

    float *qp, *kp, *vp;
    cudaGetSymbolAddress((void**)&qp, g_q);
    cudaGetSymbolAddress((void**)&kp, g_k);
    cudaGetSymbolAddress((void**)&vp, g_v);
    uint2 *ahp, *alp, *whp, *wlp;
    cudaGetSymbolAddress((void**)&ahp, g_Ahi4);
    cudaGetSymbolAddress((void**)&alp, g_Alo4);
    cudaGetSymbolAddress((void**)&whp, g_Whi4);
    cudaGetSymbolAddress((void**)&wlp, g_Wlo4);

    // split-conversion of activations and weights
    {
        int n4a = NB * TT * HIDD / 4;
        cvt_split_kernel<<<(n4a + 255) / 256, 256>>>(hs, ahp, alp, n4a);
        int n4w = HIDD * HIDD / 4;
        cvt_split_w_kernel<<<dim3((n4w + 255) / 256, 3), 256>>>(Wq, Wk, Wv,
                                                                whp, wlp, n4w);
    }

    // fused QKV projection
    {
        size_t gsmem = (size_t)(2 * STGW) * sizeof(unsigned);   // 80 KB
        cudaFuncSetAttribute(gemm_qkv_kernel,
                             cudaFuncAttributeMaxDynamicSharedMemorySize, (int)gsmem);
        dim3 ggrid(HIDD / 128, (NB * TT) / 128, 3);
        gemm_qkv_kernel<<<ggrid, 256, gsmem>>>(bq, bk, bv, qp, kp, vp);
    }

    select_kernel<<<dim3(TT / 64, NHH, NB), 64>>>(mask, bq);

    attn_global_kernel<<<dim3(TT / 64, NHH, NB), 64>>>(mask);

    size_t lsmem = (size_t)LSMEM_WORDS * sizeof(float);
    cudaFuncSetAttribute(attn_local_tc_kernel,
                         cudaFuncAttributeMaxDynamicSharedMemorySize, (int)lsmem);
    attn_local_tc_kernel<<<dim3(TT / 128, NHH, NB), 256, lsmem>>>(mask, out);

    bos_kernel<<<dim3(NHH, NB), 128>>>(mask, out);
}

// round 9
// speedup vs baseline: 2.7495x; 1.1129x over previous
#include <cuda_runtime.h>
#include <cuda_bf16.h>
#include <cuda_fp16.h>
#include <math.h>

#define NB   2
#define TT   4096
#define HIDD 1024
#define NHH  16
#define DD   64
#define TOPKK 16
#define NEGV (-10000.0f)

// ---------------- device scratch ----------------
__device__ float g_q[(size_t)NB*NHH*TT*DD];
__device__ float g_k[(size_t)NB*NHH*TT*DD];
__device__ float g_v[(size_t)NB*NHH*TT*DD];
__device__ float g_ctxg[(size_t)NB*NHH*TT*DD];
__device__ float g_lseg[(size_t)NB*NHH*TT];
__device__ float g_q0[(size_t)NB*HIDD];
__device__ int   g_gidx[(size_t)NB*NHH*(TT/4)];
__device__ int   g_lidx[(size_t)NB*NHH*(3*TT/4)];
// split planes — uint4-typed so bases are 16-byte aligned
__device__ uint4 g_Ahi4[(size_t)NB*TT*HIDD/8];   // A bf16 hi (for K gemm)
__device__ uint4 g_Alo4[(size_t)NB*TT*HIDD/8];   // A bf16 lo
__device__ uint4 g_Afh4[(size_t)NB*TT*HIDD/8];   // A fp16 hi (for Q,V gemm)
__device__ uint4 g_Afl4[(size_t)NB*TT*HIDD/8];   // A fp16 lo
__device__ uint4 g_Whi4[(size_t)HIDD*HIDD/8];    // Wk bf16 hi
__device__ uint4 g_Wlo4[(size_t)HIDD*HIDD/8];    // Wk bf16 lo
__device__ uint4 g_Wfh4[(size_t)2*HIDD*HIDD/8];  // Wq (slot0), Wv (slot1) fp16 hi

// ---------------- helpers ----------------
__device__ __forceinline__ unsigned short f2bf(float x)
{
    unsigned u = __float_as_uint(x);
    u += 0x7FFFu + ((u >> 16) & 1u);
    return (unsigned short)(u >> 16);
}
__device__ __forceinline__ float bf2f(unsigned short h)
{
    return __uint_as_float(((unsigned)h) << 16);
}

__device__ __forceinline__ void mma_bf16(float& d0, float& d1, float& d2, float& d3,
                                         unsigned a0, unsigned a1, unsigned a2, unsigned a3,
                                         unsigned b0, unsigned b1)
{
    asm volatile(
        "mma.sync.aligned.m16n8k16.row.col.f32.bf16.bf16.f32 "
        "{%0,%1,%2,%3}, {%4,%5,%6,%7}, {%8,%9}, {%0,%1,%2,%3};\n"
        : "+f"(d0), "+f"(d1), "+f"(d2), "+f"(d3)
        : "r"(a0), "r"(a1), "r"(a2), "r"(a3), "r"(b0), "r"(b1));
}
__device__ __forceinline__ void mma_f16(float& d0, float& d1, float& d2, float& d3,
                                        unsigned a0, unsigned a1, unsigned a2, unsigned a3,
                                        unsigned b0, unsigned b1)
{
    asm volatile(
        "mma.sync.aligned.m16n8k16.row.col.f32.f16.f16.f32 "
        "{%0,%1,%2,%3}, {%4,%5,%6,%7}, {%8,%9}, {%0,%1,%2,%3};\n"
        : "+f"(d0), "+f"(d1), "+f"(d2), "+f"(d3)
        : "r"(a0), "r"(a1), "r"(a2), "r"(a3), "r"(b0), "r"(b1));
}

__device__ __forceinline__ void ldsm4(unsigned& r0, unsigned& r1,
                                      unsigned& r2, unsigned& r3, unsigned saddr)
{
    asm volatile("ldmatrix.sync.aligned.m8n8.x4.shared.b16 {%0,%1,%2,%3}, [%4];"
                 : "=r"(r0), "=r"(r1), "=r"(r2), "=r"(r3) : "r"(saddr));
}

__device__ __forceinline__ void cp16(void* smem_dst, const void* gsrc)
{
    unsigned saddr = (unsigned)__cvta_generic_to_shared(smem_dst);
    asm volatile("cp.async.ca.shared.global [%0], [%1], 16;\n"
                 :: "r"(saddr), "l"(gsrc));
}
__device__ __forceinline__ void cp_commit()
{
    asm volatile("cp.async.commit_group;\n" ::: "memory");
}
template <int N> __device__ __forceinline__ void cp_wait()
{
    asm volatile("cp.async.wait_group %0;\n" :: "n"(N) : "memory");
}

// ---------------- conversions ------------------------------------------------------
__global__ void cvt_a_kernel(const float* __restrict__ in,
                             uint2* __restrict__ bh, uint2* __restrict__ bl,
                             uint2* __restrict__ fh, uint2* __restrict__ fl, int n4)
{
    int i = blockIdx.x * blockDim.x + threadIdx.x;
    if (i >= n4) return;
    float4 v = ((const float4*)in)[i];
    // bf16 hi/lo
    unsigned short h0 = f2bf(v.x), h1 = f2bf(v.y), h2 = f2bf(v.z), h3 = f2bf(v.w);
    unsigned short l0 = f2bf(v.x - bf2f(h0)), l1 = f2bf(v.y - bf2f(h1));
    unsigned short l2 = f2bf(v.z - bf2f(h2)), l3 = f2bf(v.w - bf2f(h3));
    bh[i] = make_uint2((unsigned)h0 | ((unsigned)h1 << 16),
                       (unsigned)h2 | ((unsigned)h3 << 16));
    bl[i] = make_uint2((unsigned)l0 | ((unsigned)l1 << 16),
                       (unsigned)l2 | ((unsigned)l3 << 16));
    // fp16 hi/lo
    __half fh0 = __float2half_rn(v.x), fh1 = __float2half_rn(v.y);
    __half fh2 = __float2half_rn(v.z), fh3 = __float2half_rn(v.w);
    __half fl0 = __float2half_rn(v.x - __half2float(fh0));
    __half fl1 = __float2half_rn(v.y - __half2float(fh1));
    __half fl2 = __float2half_rn(v.z - __half2float(fh2));
    __half fl3 = __float2half_rn(v.w - __half2float(fh3));
    fh[i] = make_uint2((unsigned)__half_as_ushort(fh0) | ((unsigned)__half_as_ushort(fh1) << 16),
                       (unsigned)__half_as_ushort(fh2) | ((unsigned)__half_as_ushort(fh3) << 16));
    fl[i] = make_uint2((unsigned)__half_as_ushort(fl0) | ((unsigned)__half_as_ushort(fl1) << 16),
                       (unsigned)__half_as_ushort(fl2) | ((unsigned)__half_as_ushort(fl3) << 16));
}

// y==0: Wq->fp16 slot0; y==1: Wk->bf16; y==2: Wv->fp16 slot1
__global__ void cvt_w_kernel(const float* __restrict__ Wq,
                             const float* __restrict__ Wk,
                             const float* __restrict__ Wv,
                             uint2* __restrict__ bh, uint2* __restrict__ bl,
                             uint2* __restrict__ fh, int n4)
{
    int i = blockIdx.x * blockDim.x + threadIdx.x;
    if (i >= n4) return;
    int w = blockIdx.y;
    if (w == 1) {
        float4 v = ((const float4*)Wk)[i];
        unsigned short h0 = f2bf(v.x), h1 = f2bf(v.y), h2 = f2bf(v.z), h3 = f2bf(v.w);
        unsigned short l0 = f2bf(v.x - bf2f(h0)), l1 = f2bf(v.y - bf2f(h1));
        unsigned short l2 = f2bf(v.z - bf2f(h2)), l3 = f2bf(v.w - bf2f(h3));
        bh[i] = make_uint2((unsigned)h0 | ((unsigned)h1 << 16),
                           (unsigned)h2 | ((unsigned)h3 << 16));
        bl[i] = make_uint2((unsigned)l0 | ((unsigned)l1 << 16),
                           (unsigned)l2 | ((unsigned)l3 << 16));
    } else {
        const float* in = (w == 0) ? Wq : Wv;
        int slot = (w == 0) ? 0 : 1;
        float4 v = ((const float4*)in)[i];
        __half fh0 = __float2half_rn(v.x), fh1 = __float2half_rn(v.y);
        __half fh2 = __float2half_rn(v.z), fh3 = __float2half_rn(v.w);
        fh[(size_t)slot * n4 + i] =
            make_uint2((unsigned)__half_as_ushort(fh0) | ((unsigned)__half_as_ushort(fh1) << 16),
                       (unsigned)__half_as_ushort(fh2) | ((unsigned)__half_as_ushort(fh3) << 16));
    }
}

// exact fp32 q for token 0 (feeds BOS): q0[n, c] = hs[n,0,:]·Wq[c,:] + bq[c]
__global__ void q0_kernel(const float* __restrict__ hs,
                          const float* __restrict__ Wq,
                          const float* __restrict__ bq)
{
    const int c = blockIdx.x;
    const int n = blockIdx.y;
    const int tid = threadIdx.x;   // 128
    __shared__ float red[128];
    const float* xr = hs + (size_t)n * TT * HIDD;
    const float* wr = Wq + (size_t)c * HIDD;
    float pa = 0.0f;
    for (int k = tid; k < HIDD; k += 128) pa = fmaf(xr[k], wr[k], pa);
    red[tid] = pa;
    __syncthreads();
    for (int off = 64; off > 0; off >>= 1) {
        if (tid < off) red[tid] += red[tid + off];
        __syncthreads();
    }
    if (tid == 0) g_q0[(size_t)n * HIDD + c] = red[0] + bq[c];
}

// ============= K GEMM: 3-term split-bf16 (exact-enough for top-k selection) ========
#define GSTR 20                       /* row stride in words (80 bytes) */
#define PLW  (128 * GSTR)             /* words per plane = 2560 */
#define PA_HI 0
#define PA_LO (1 * PLW)
#define PB_HI (2 * PLW)
#define PB_LO (3 * PLW)
#define STGW  (4 * PLW)

__device__ __forceinline__ void k_load_stage(unsigned* st,
                                             const __nv_bfloat16* Ah,
                                             const __nv_bfloat16* Al,
                                             const __nv_bfloat16* Wh,
                                             const __nv_bfloat16* Wl,
                                             int kofs, int tid)
{
#pragma unroll
    for (int i = 0; i < 2; i++) {
        int c = tid + i * 256;
        int row = c >> 2;
        int cw = c & 3;
        size_t go = (size_t)row * HIDD + kofs + cw * 8;
        unsigned* sp = st + row * GSTR + cw * 4;
        cp16(sp + PA_HI, Ah + go);
        cp16(sp + PA_LO, Al + go);
        cp16(sp + PB_HI, Wh + go);
        cp16(sp + PB_LO, Wl + go);
    }
    cp_commit();
}

__global__ __launch_bounds__(256, 2)
void gemm_k_kernel(const float* __restrict__ bk, float* __restrict__ ok)
{
    extern __shared__ unsigned gsm[];
    const int tid = threadIdx.x;
    const int m0 = blockIdx.y * 128;
    const int n0 = blockIdx.x * 128;

    const __nv_bfloat16* Ah = (const __nv_bfloat16*)g_Ahi4 + (size_t)m0 * HIDD;
    const __nv_bfloat16* Al = (const __nv_bfloat16*)g_Alo4 + (size_t)m0 * HIDD;
    const __nv_bfloat16* Wh = (const __nv_bfloat16*)g_Whi4 + (size_t)n0 * HIDD;
    const __nv_bfloat16* Wl = (const __nv_bfloat16*)g_Wlo4 + (size_t)n0 * HIDD;

    const int lane = tid & 31;
    const int warp = tid >> 5;
    const int wm = warp >> 1;
    const int wn = warp & 1;
    const int qr = lane >> 2;
    const int qc = lane & 3;
    const int rA = wm * 32;
    const int cB = wn * 64;

    const unsigned smem_base = (unsigned)__cvta_generic_to_shared(gsm);
    const int a_row = rA + (lane & 7) + ((lane >> 3) & 1) * 8;
    const unsigned a_k = ((lane >> 4) & 1) * 16;
    const int b_row = cB + (lane & 7) + ((lane >> 4) & 1) * 8;
    const unsigned b_k = ((lane >> 3) & 1) * 16;

    float acc[2][8][4];
#pragma unroll
    for (int mt = 0; mt < 2; mt++)
#pragma unroll
        for (int nt = 0; nt < 8; nt++)
#pragma unroll
            for (int e = 0; e < 4; e++) acc[mt][nt][e] = 0.0f;

    k_load_stage(gsm, Ah, Al, Wh, Wl, 0, tid);

    const int NIT = HIDD / 32;
    for (int it = 0; it < NIT; it++) {
        if (it + 1 < NIT) {
            k_load_stage(gsm + ((it + 1) & 1) * STGW, Ah, Al, Wh, Wl, (it + 1) * 32, tid);
            cp_wait<1>();
        } else {
            cp_wait<0>();
        }
        __syncthreads();

        const unsigned sb = smem_base + ((it & 1) * STGW) * 4;
#pragma unroll
        for (int s = 0; s < 2; s++) {
            unsigned a_hi[2][4], a_lo[2][4];
#pragma unroll
            for (int mt = 0; mt < 2; mt++) {
                unsigned ao = (unsigned)(a_row + mt * 16) * 80 + s * 32 + a_k;
                ldsm4(a_hi[mt][0], a_hi[mt][1], a_hi[mt][2], a_hi[mt][3],
                      sb + PA_HI * 4 + ao);
                ldsm4(a_lo[mt][0], a_lo[mt][1], a_lo[mt][2], a_lo[mt][3],
                      sb + PA_LO * 4 + ao);
            }
#pragma unroll
            for (int p = 0; p < 4; p++) {
                unsigned bo = (unsigned)(b_row + p * 16) * 80 + s * 32 + b_k;
                unsigned bh0a, bh1a, bh0b, bh1b, bl0a, bl1a, bl0b, bl1b;
                ldsm4(bh0a, bh1a, bh0b, bh1b, sb + PB_HI * 4 + bo);
                ldsm4(bl0a, bl1a, bl0b, bl1b, sb + PB_LO * 4 + bo);
#pragma unroll
                for (int mt = 0; mt < 2; mt++) {
                    float* c0 = acc[mt][2 * p];
                    mma_bf16(c0[0], c0[1], c0[2], c0[3],
                             a_hi[mt][0], a_hi[mt][1], a_hi[mt][2], a_hi[mt][3], bh0a, bh1a);
                    mma_bf16(c0[0], c0[1], c0[2], c0[3],
                             a_hi[mt][0], a_hi[mt][1], a_hi[mt][2], a_hi[mt][3], bl0a, bl1a);
                    mma_bf16(c0[0], c0[1], c0[2], c0[3],
                             a_lo[mt][0], a_lo[mt][1], a_lo[mt][2], a_lo[mt][3], bh0a, bh1a);
                    float* c1 = acc[mt][2 * p + 1];
                    mma_bf16(c1[0], c1[1], c1[2], c1[3],
                             a_hi[mt][0], a_hi[mt][1], a_hi[mt][2], a_hi[mt][3], bh0b, bh1b);
                    mma_bf16(c1[0], c1[1], c1[2], c1[3],
                             a_hi[mt][0], a_hi[mt][1], a_hi[mt][2], a_hi[mt][3], bl0b, bl1b);
                    mma_bf16(c1[0], c1[1], c1[2], c1[3],
                             a_lo[mt][0], a_lo[mt][1], a_lo[mt][2], a_lo[mt][3], bh0b, bh1b);
                }
            }
        }
        __syncthreads();
    }

#pragma unroll
    for (int mt = 0; mt < 2; mt++) {
#pragma unroll
        for (int nt = 0; nt < 8; nt++) {
#pragma unroll
            for (int half = 0; half < 2; half++) {
                int row = m0 + rA + mt * 16 + qr + half * 8;
                int nb  = row >> 12;
                int t   = row & (TT - 1);
                int col = n0 + cB + nt * 8 + qc * 2;
                int h = col >> 6;
                int d = col & 63;
                float* op = ok + (((size_t)(nb * NHH + h)) * TT + t) * DD + d;
                op[0] = acc[mt][nt][half * 2 + 0] + bk[col];
                op[1] = acc[mt][nt][half * 2 + 1] + bk[col + 1];
            }
        }
    }
}

// ============= Q/V GEMM: 2-term fp16 split (A·hi(B)), 3 smem planes ===============
#define QV_PA_HI 0
#define QV_PA_LO (1 * PLW)
#define QV_PB_HI (2 * PLW)
#define QV_STGW  (3 * PLW)

__device__ __forceinline__ void qv_load_stage(unsigned* st,
                                              const __half* Ah, const __half* Al,
                                              const __half* Wh, int kofs, int tid)
{
#pragma unroll
    for (int i = 0; i < 2; i++) {
        int c = tid + i * 256;
        int row = c >> 2;
        int cw = c & 3;
        size_t go = (size_t)row * HIDD + kofs + cw * 8;
        unsigned* sp = st + row * GSTR + cw * 4;
        cp16(sp + QV_PA_HI, Ah + go);
        cp16(sp + QV_PA_LO, Al + go);
        cp16(sp + QV_PB_HI, Wh + go);
    }
    cp_commit();
}

__global__ __launch_bounds__(256, 2)
void gemm_qv_kernel(const float* __restrict__ bq, const float* __restrict__ bv,
                    float* __restrict__ oq, float* __restrict__ ov)
{
    extern __shared__ unsigned gsm[];
    const int tid = threadIdx.x;
    const int m0 = blockIdx.y * 128;
    const int n0 = blockIdx.x * 128;
    const int z  = blockIdx.z;       // 0 = Q, 1 = V

    const __half* Ah = (const __half*)g_Afh4 + (size_t)m0 * HIDD;
    const __half* Al = (const __half*)g_Afl4 + (size_t)m0 * HIDD;
    const __half* Wh = (const __half*)g_Wfh4 + ((size_t)z * HIDD + n0) * HIDD;
    const float* bias = z ? bv : bq;
    float* out = z ? ov : oq;

    const int lane = tid & 31;
    const int warp = tid >> 5;
    const int wm = warp >> 1;
    const int wn = warp & 1;
    const int qr = lane >> 2;
    const int qc = lane & 3;
    const int rA = wm * 32;
    const int cB = wn * 64;

    const unsigned smem_base = (unsigned)__cvta_generic_to_shared(gsm);
    const int a_row = rA + (lane & 7) + ((lane >> 3) & 1) * 8;
    const unsigned a_k = ((lane >> 4) & 1) * 16;
    const int b_row = cB + (lane & 7) + ((lane >> 4) & 1) * 8;
    const unsigned b_k = ((lane >> 3) & 1) * 16;

    float acc[2][8][4];
#pragma unroll
    for (int mt = 0; mt < 2; mt++)
#pragma unroll
        for (int nt = 0; nt < 8; nt++)
#pragma unroll
            for (int e = 0; e < 4; e++) acc[mt][nt][e] = 0.0f;

    qv_load_stage(gsm, Ah, Al, Wh, 0, tid);

    const int NIT = HIDD / 32;
    for (int it = 0; it < NIT; it++) {
        if (it + 1 < NIT) {
            qv_load_stage(gsm + ((it + 1) & 1) * QV_STGW, Ah, Al, Wh, (it + 1) * 32, tid);
            cp_wait<1>();
        } else {
            cp_wait<0>();
        }
        __syncthreads();

        const unsigned sb = smem_base + ((it & 1) * QV_STGW) * 4;
#pragma unroll
        for (int s = 0; s < 2; s++) {
            unsigned a_hi[2][4], a_lo[2][4];
#pragma unroll
            for (int mt = 0; mt < 2; mt++) {
                unsigned ao = (unsigned)(a_row + mt * 16) * 80 + s * 32 + a_k;
                ldsm4(a_hi[mt][0], a_hi[mt][1], a_hi[mt][2], a_hi[mt][3],
                      sb + QV_PA_HI * 4 + ao);
                ldsm4(a_lo[mt][0], a_lo[mt][1], a_lo[mt][2], a_lo[mt][3],
                      sb + QV_PA_LO * 4 + ao);
            }
#pragma unroll
            for (int p = 0; p < 4; p++) {
                unsigned bo = (unsigned)(b_row + p * 16) * 80 + s * 32 + b_k;
                unsigned bh0a, bh1a, bh0b, bh1b;
                ldsm4(bh0a, bh1a, bh0b, bh1b, sb + QV_PB_HI * 4 + bo);
#pragma unroll
                for (int mt = 0; mt < 2; mt++) {
                    float* c0 = acc[mt][2 * p];
                    mma_f16(c0[0], c0[1], c0[2], c0[3],
                            a_hi[mt][0], a_hi[mt][1], a_hi[mt][2], a_hi[mt][3], bh0a, bh1a);
                    mma_f16(c0[0], c0[1], c0[2], c0[3],
                            a_lo[mt][0], a_lo[mt][1], a_lo[mt][2], a_lo[mt][3], bh0a, bh1a);
                    float* c1 = acc[mt][2 * p + 1];
                    mma_f16(c1[0], c1[1], c1[2], c1[3],
                            a_hi[mt][0], a_hi[mt][1], a_hi[mt][2], a_hi[mt][3], bh0b, bh1b);
                    mma_f16(c1[0], c1[1], c1[2], c1[3],
                            a_lo[mt][0], a_lo[mt][1], a_lo[mt][2], a_lo[mt][3], bh0b, bh1b);
                }
            }
        }
        __syncthreads();
    }

#pragma unroll
    for (int mt = 0; mt < 2; mt++) {
#pragma unroll
        for (int nt = 0; nt < 8; nt++) {
#pragma unroll
            for (int half = 0; half < 2; half++) {
                int row = m0 + rA + mt * 16 + qr + half * 8;
                int nb  = row >> 12;
                int t   = row & (TT - 1);
                int col = n0 + cB + nt * 8 + qc * 2;
                int h = col >> 6;
                int d = col & 63;
                float* op = out + (((size_t)(nb * NHH + h)) * TT + t) * DD + d;
                op[0] = acc[mt][nt][half * 2 + 0] + bias[col];
                op[1] = acc[mt][nt][half * 2 + 1] + bias[col + 1];
            }
        }
    }
}

// ---------------- norm-based top-k selection per 64-token block -------------------
__global__ void select_kernel(const float* __restrict__ mask,
                              const float* __restrict__ bq)
{
    const int blk = blockIdx.x;
    const int h   = blockIdx.y;
    const int n   = blockIdx.z;
    const int i   = threadIdx.x;
    __shared__ float norms[64];
    __shared__ int flags[64];

    const int token = blk * 64 + i;
    const float* kr = g_k + (((size_t)(n * NHH + h)) * TT + token) * DD;
    const float* bqr = bq + h * DD;
    float s = 0.0f;
#pragma unroll
    for (int d = 0; d < DD; d++) { float vv = kr[d] + bqr[d]; s += vv * vv; }
    if (mask[n * TT + token] != 0.0f) s = 0.0f;
    norms[i] = s;
    __syncthreads();

    float mine = norms[i];
    int rank = 0;
    for (int j = 0; j < 64; j++) {
        float nj = norms[j];
        rank += (nj < mine) || (nj == mine && j < i);
    }
    int top = (rank >= 64 - TOPKK) ? 1 : 0;
    flags[i] = top;
    __syncthreads();

    int pos = 0;
    for (int j = 0; j < i; j++) pos += flags[j];
    if (top)
        g_gidx[((size_t)(n * NHH + h)) * (TT / 4) + blk * TOPKK + pos] = token;
    else
        g_lidx[((size_t)(n * NHH + h)) * (3 * TT / 4) + blk * 48 + (i - pos)] = token;
}

// ---------------- global pass: 64 queries x 48 gathered keys ----------------------
__global__ void attn_global_kernel(const float* __restrict__ mask)
{
    const int qb = blockIdx.x;
    const int h  = blockIdx.y;
    const int n  = blockIdx.z;
    const int tid = threadIdx.x;
    __shared__ float ks[48 * 64];
    __shared__ float vs[48 * 64];
    __shared__ float ms[48];
    __shared__ float sc[64 * 49];

    const size_t ho = (size_t)(n * NHH + h);
    const float* kb = g_k + ho * TT * DD;
    const float* vb = g_v + ho * TT * DD;
    const int* gix = g_gidx + ho * (TT / 4);

    for (int idx = tid; idx < 48 * 64; idx += 64) {
        int r = idx >> 6, c = idx & 63;
        int g = qb * 16 - 16 + r;
        float kvv = 0.0f, vvv = 0.0f;
        if (g >= 0 && g < TT / 4) {
            int src = gix[g];
            kvv = kb[(size_t)src * DD + c];
            vvv = vb[(size_t)src * DD + c];
            if (c == 0) ms[r] = mask[n * TT + src];
        } else {
            if (c == 0) ms[r] = NEGV;
        }
        ks[idx] = kvv; vs[idx] = vvv;
    }
    __syncthreads();

    const int qi = tid;
    const int tq = qb * 64 + qi;
    const float* qr = g_q + (ho * TT + tq) * DD;
    float qreg[64];
#pragma unroll
    for (int d = 0; d < 64; d++) qreg[d] = qr[d];

    float* row = sc + qi * 49;
    float mmax = -1e30f;
    for (int kk = 0; kk < 48; kk++) {
        float dot = 0.0f;
#pragma unroll
        for (int d = 0; d < 64; d++) dot = fmaf(qreg[d], ks[kk * 64 + d], dot);
        float s = dot * 0.125f + ms[kk];
        row[kk] = s;
        mmax = fmaxf(mmax, s);
    }
    float l = 0.0f;
    for (int kk = 0; kk < 48; kk++) {
        float p = __expf(row[kk] - mmax);
        row[kk] = p;
        l += p;
    }
    g_lseg[ho * TT + tq] = mmax + logf(l);
    float inv = 1.0f / l;
    float* ctxr = g_ctxg + (ho * TT + tq) * DD;
    for (int d0 = 0; d0 < 64; d0 += 32) {
        float acc[32];
#pragma unroll
        for (int dd = 0; dd < 32; dd++) acc[dd] = 0.0f;
        for (int kk = 0; kk < 48; kk++) {
            float w = row[kk];
#pragma unroll
            for (int dd = 0; dd < 32; dd++)
                acc[dd] = fmaf(w, vs[kk * 64 + d0 + dd], acc[dd]);
        }
#pragma unroll
        for (int dd = 0; dd < 32; dd++) ctxr[d0 + dd] = acc[dd] * inv;
    }
}

// ============== local pass: tf32 flash, P via register shuffles (no smem P) =======
#define KC     112
#define NCHK   3
#define QSTRW  68
#define VSTRW  72
#define QS_OFF 0
#define KS_OFF (QS_OFF + 128*QSTRW)
#define VS_OFF (KS_OFF + KC*QSTRW)
#define MS_OFF (VS_OFF + KC*VSTRW)
#define LSMEM_WORDS (MS_OFF + KC)     /* 24496 words = 97984 B */

__device__ __forceinline__ float to_tf32(float x)
{
    float r;
    asm("cvt.rna.tf32.f32 %0, %1;" : "=f"(r) : "f"(x));
    return r;
}

__device__ __forceinline__ void mma_tf32(float& d0, float& d1, float& d2, float& d3,
                                         float a0, float a1, float a2, float a3,
                                         float b0, float b1)
{
    asm volatile(
        "mma.sync.aligned.m16n8k8.row.col.f32.tf32.tf32.f32 "
        "{%0,%1,%2,%3}, {%4,%5,%6,%7}, {%8,%9}, {%0,%1,%2,%3};\n"
        : "+f"(d0), "+f"(d1), "+f"(d2), "+f"(d3)
        : "r"(__float_as_uint(a0)), "r"(__float_as_uint(a1)),
          "r"(__float_as_uint(a2)), "r"(__float_as_uint(a3)),
          "r"(__float_as_uint(b0)), "r"(__float_as_uint(b1)));
}

__global__ __launch_bounds__(256, 2)
void attn_local_tc_kernel(const float* __restrict__ mask,
                          float* __restrict__ out)
{
    extern __shared__ float sm[];
    float* Qs = sm + QS_OFF;
    float* Ks = sm + KS_OFF;
    float* Vs = sm + VS_OFF;
    float* Ms = sm + MS_OFF;

    const int qb = blockIdx.x;
    const int h  = blockIdx.y;
    const int n  = blockIdx.z;
    const int tid = threadIdx.x;
    const int lane = tid & 31;
    const int warp = tid >> 5;
    const int qr = lane >> 2;
    const int qc = lane & 3;
    const int w16 = warp * 16;

    const size_t ho = (size_t)(n * NHH + h);
    const float* kb = g_k + ho * TT * DD;
    const float* vb = g_v + ho * TT * DD;
    const int* lix = g_lidx + ho * (3 * TT / 4);

#pragma unroll
    for (int i = 0; i < 8; i++) {
        int idx = tid + i * 256;
        int r = idx >> 4, c4 = idx & 15;
        const float4 qv = *(const float4*)(g_q + (ho * TT + qb * 128 + r) * DD + c4 * 4);
        float* dst = Qs + r * QSTRW + c4 * 4;
        dst[0] = to_tf32(qv.x); dst[1] = to_tf32(qv.y);
        dst[2] = to_tf32(qv.z); dst[3] = to_tf32(qv.w);
    }

    float m0 = -1e30f, m1 = -1e30f, l0 = 0.0f, l1 = 0.0f;
    float o[8][4];
#pragma unroll
    for (int nt = 0; nt < 8; nt++)
#pragma unroll
        for (int e = 0; e < 4; e++) o[nt][e] = 0.0f;

    for (int ch = 0; ch < NCHK; ch++) {
        __syncthreads();
        for (int idx = tid; idx < KC * 16; idx += 256) {
            int r = idx >> 4, c4 = idx & 15;
            int kk = ch * KC + r;
            float4 kv = make_float4(0.f, 0.f, 0.f, 0.f);
            float4 vv = make_float4(0.f, 0.f, 0.f, 0.f);
            float mval = -1e30f;
            if (kk < 288) {
                int g = qb * 96 - 96 + kk;
                if (g >= 0 && g < 3 * TT / 4) {
                    int src = lix[g];
                    kv = *(const float4*)(kb + (size_t)src * DD + c4 * 4);
                    vv = *(const float4*)(vb + (size_t)src * DD + c4 * 4);
                    mval = mask[n * TT + src];
                } else {
                    mval = NEGV;
                }
            } else if (kk == 288) {
                kv = *(const float4*)(kb + c4 * 4);
                vv = *(const float4*)(vb + c4 * 4);
                mval = 0.0f;
            }
            float* kd = Ks + r * QSTRW + c4 * 4;
            kd[0] = to_tf32(kv.x); kd[1] = to_tf32(kv.y);
            kd[2] = to_tf32(kv.z); kd[3] = to_tf32(kv.w);
            float* vd = Vs + r * VSTRW + c4 * 4;
            vd[0] = to_tf32(vv.x); vd[1] = to_tf32(vv.y);
            vd[2] = to_tf32(vv.z); vd[3] = to_tf32(vv.w);
            if (c4 == 0) Ms[r] = mval;
        }
        __syncthreads();

        float s[14][4];
#pragma unroll
        for (int nt = 0; nt < 14; nt++)
#pragma unroll
            for (int e = 0; e < 4; e++) s[nt][e] = 0.0f;

#pragma unroll
        for (int k8 = 0; k8 < 8; k8++) {
            const int kc0 = k8 * 8 + qc;
            float a0 = Qs[(w16 + qr) * QSTRW + kc0];
            float a1 = Qs[(w16 + qr + 8) * QSTRW + kc0];
            float a2 = Qs[(w16 + qr) * QSTRW + kc0 + 4];
            float a3 = Qs[(w16 + qr + 8) * QSTRW + kc0 + 4];
#pragma unroll
            for (int nt = 0; nt < 14; nt++) {
                float b0 = Ks[(nt * 8 + qr) * QSTRW + kc0];
                float b1 = Ks[(nt * 8 + qr) * QSTRW + kc0 + 4];
                mma_tf32(s[nt][0], s[nt][1], s[nt][2], s[nt][3],
                         a0, a1, a2, a3, b0, b1);
            }
        }

        float cmax0 = -1e30f, cmax1 = -1e30f;
#pragma unroll
        for (int nt = 0; nt < 14; nt++) {
            float mc0 = Ms[nt * 8 + 2 * qc];
            float mc1 = Ms[nt * 8 + 2 * qc + 1];
            s[nt][0] = s[nt][0] * 0.125f + mc0;
            s[nt][1] = s[nt][1] * 0.125f + mc1;
            s[nt][2] = s[nt][2] * 0.125f + mc0;
            s[nt][3] = s[nt][3] * 0.125f + mc1;
            cmax0 = fmaxf(cmax0, fmaxf(s[nt][0], s[nt][1]));
            cmax1 = fmaxf(cmax1, fmaxf(s[nt][2], s[nt][3]));
        }
        cmax0 = fmaxf(cmax0, __shfl_xor_sync(0xffffffffu, cmax0, 1));
        cmax0 = fmaxf(cmax0, __shfl_xor_sync(0xffffffffu, cmax0, 2));
        cmax1 = fmaxf(cmax1, __shfl_xor_sync(0xffffffffu, cmax1, 1));
        cmax1 = fmaxf(cmax1, __shfl_xor_sync(0xffffffffu, cmax1, 2));

        float mn0 = fmaxf(m0, cmax0);
        float mn1 = fmaxf(m1, cmax1);
        float corr0 = __expf(m0 - mn0);
        float corr1 = __expf(m1 - mn1);
        m0 = mn0; m1 = mn1;

        // P = exp(S - m): keep tf32-rounded P in s[][], raw sums in rs
        float rs0 = 0.0f, rs1 = 0.0f;
#pragma unroll
        for (int nt = 0; nt < 14; nt++) {
            float p0 = __expf(s[nt][0] - mn0);
            float p1 = __expf(s[nt][1] - mn0);
            float p2 = __expf(s[nt][2] - mn1);
            float p3 = __expf(s[nt][3] - mn1);
            rs0 += p0 + p1; rs1 += p2 + p3;
            s[nt][0] = to_tf32(p0); s[nt][1] = to_tf32(p1);
            s[nt][2] = to_tf32(p2); s[nt][3] = to_tf32(p3);
        }
        rs0 += __shfl_xor_sync(0xffffffffu, rs0, 1);
        rs0 += __shfl_xor_sync(0xffffffffu, rs0, 2);
        rs1 += __shfl_xor_sync(0xffffffffu, rs1, 1);
        rs1 += __shfl_xor_sync(0xffffffffu, rs1, 2);
        l0 = l0 * corr0 + rs0;
        l1 = l1 * corr1 + rs1;

#pragma unroll
        for (int nt = 0; nt < 8; nt++) {
            o[nt][0] *= corr0; o[nt][1] *= corr0;
            o[nt][2] *= corr1; o[nt][3] *= corr1;
        }

        // O += P * V with C->A fragment conversion via shuffles
        const int src0 = (qr << 2) + (qc >> 1);
        const int src2 = src0 + 2;
        const bool odd = (qc & 1) != 0;
#pragma unroll
        for (int kt = 0; kt < 14; kt++) {
            float p0 = s[kt][0], p1 = s[kt][1], p2 = s[kt][2], p3 = s[kt][3];
            float t0 = __shfl_sync(0xffffffffu, p0, src0);
            float t1 = __shfl_sync(0xffffffffu, p1, src0);
            float t2 = __shfl_sync(0xffffffffu, p2, src0);
            float t3 = __shfl_sync(0xffffffffu, p3, src0);
            float u0 = __shfl_sync(0xffffffffu, p0, src2);
            float u1 = __shfl_sync(0xffffffffu, p1, src2);
            float u2 = __shfl_sync(0xffffffffu, p2, src2);
            float u3 = __shfl_sync(0xffffffffu, p3, src2);
            float a0 = odd ? t1 : t0;   // P(qr,   qc)
            float a1 = odd ? t3 : t2;   // P(qr+8, qc)
            float a2 = odd ? u1 : u0;   // P(qr,   qc+4)
            float a3 = odd ? u3 : u2;   // P(qr+8, qc+4)
#pragma unroll
            for (int nt = 0; nt < 8; nt++) {
                float b0 = Vs[(kt * 8 + qc) * VSTRW + nt * 8 + qr];
                float b1 = Vs[(kt * 8 + qc + 4) * VSTRW + nt * 8 + qr];
                mma_tf32(o[nt][0], o[nt][1], o[nt][2], o[nt][3],
                         a0, a1, a2, a3, b0, b1);
            }
        }
    }

    float lse0 = m0 + logf(l0);
    float lse1 = m1 + logf(l1);
    float inv0 = 1.0f / l0;
    float inv1 = 1.0f / l1;

    int row0 = qb * 128 + w16 + qr;
    int row1 = row0 + 8;
    float lg0 = g_lseg[ho * TT + row0];
    float lg1 = g_lseg[ho * TT + row1];
    float pm0 = 1.0f / (1.0f + __expf(lg0 - lse0));
    float pm1 = 1.0f / (1.0f + __expf(lg1 - lse1));

    const float* cg0 = g_ctxg + (ho * TT + row0) * DD;
    const float* cg1 = g_ctxg + (ho * TT + row1) * DD;
    float* op0 = out + ((size_t)n * TT + row0) * HIDD + h * DD;
    float* op1 = out + ((size_t)n * TT + row1) * HIDD + h * DD;

#pragma unroll
    for (int nt = 0; nt < 8; nt++) {
        int c0 = nt * 8 + 2 * qc;
#pragma unroll
        for (int e = 0; e < 2; e++) {
            float cl0 = o[nt][e] * inv0;
            float cv0 = cg0[c0 + e];
            op0[c0 + e] = cv0 + pm0 * (cl0 - cv0);
            float cl1 = o[nt][2 + e] * inv1;
            float cv1 = cg1[c0 + e];
            op1[c0 + e] = cv1 + pm1 * (cl1 - cv1);
        }
    }
}

// ---------------- BOS row (exact q from g_q0) --------------------------------------
__global__ void bos_kernel(const float* __restrict__ mask,
                           float* __restrict__ out)
{
    const int h = blockIdx.x;
    const int n = blockIdx.y;
    const int tid = threadIdx.x;
    __shared__ float sc[TT];
    __shared__ float qs[64];
    __shared__ float red[128];

    const size_t ho = (size_t)(n * NHH + h);
    const float* kb = g_k + ho * TT * DD;
    const float* vb = g_v + ho * TT * DD;
    if (tid < 64) qs[tid] = g_q0[(size_t)n * HIDD + h * DD + tid];
    __syncthreads();

    float lmax = -1e30f;
    for (int t = tid; t < TT; t += 128) {
        const float* kr = kb + (size_t)t * DD;
        float dot = 0.0f;
#pragma unroll
        for (int d = 0; d < 64; d++) dot = fmaf(qs[d], kr[d], dot);
        float s = dot + mask[n * TT + t];
        sc[t] = s;
        lmax = fmaxf(lmax, s);
    }
    red[tid] = lmax;
    __syncthreads();
    for (int off = 64; off > 0; off >>= 1) {
        if (tid < off) red[tid] = fmaxf(red[tid], red[tid + off]);
        __syncthreads();
    }
    float mmax = red[0];
    float lsum = 0.0f;
    for (int t = tid; t < TT; t += 128) {
        float p = __expf(sc[t] - mmax);
        sc[t] = p;
        lsum += p;
    }
    __syncthreads();
    red[tid] = lsum;
    __syncthreads();
    for (int off = 64; off > 0; off >>= 1) {
        if (tid < off) red[tid] += red[tid + off];
        __syncthreads();
    }
    float inv = 1.0f / red[0];
    if (tid < 64) {
        int d = tid;
        float acc = 0.0f;
        for (int t = 0; t < TT; t++)
            acc = fmaf(sc[t], vb[(size_t)t * DD + d], acc);
        out[((size_t)n * TT) * HIDD + h * DD + d] = acc * inv;
    }
}

// ---------------- launch ----------------------------------------------------------
extern "C" void kernel_launch(void* const* d_in, const int* in_sizes, int n_in,
                              void* d_out, int out_size)
{
    (void)in_sizes; (void)n_in; (void)out_size;
    const float* hs   = (const float*)d_in[0];
    const float* mask = (const float*)d_in[1];
    const float* Wq   = (const float*)d_in[2];
    const float* bq   = (const float*)d_in[3];
    const float* Wk   = (const float*)d_in[4];
    const float* bk   = (const float*)d_in[5];
    const float* Wv   = (const float*)d_in[6];
    const float* bv   = (const float*)d_in[7];
    float* out = (float*)d_out;

    float *qp, *kp, *vp;
    cudaGetSymbolAddress((void**)&qp, g_q);
    cudaGetSymbolAddress((void**)&kp, g_k);
    cudaGetSymbolAddress((void**)&vp, g_v);
    uint2 *ahp, *alp, *afh, *afl, *whp, *wlp, *wfh;
    cudaGetSymbolAddress((void**)&ahp, g_Ahi4);
    cudaGetSymbolAddress((void**)&alp, g_Alo4);
    cudaGetSymbolAddress((void**)&afh, g_Afh4);
    cudaGetSymbolAddress((void**)&afl, g_Afl4);
    cudaGetSymbolAddress((void**)&whp, g_Whi4);
    cudaGetSymbolAddress((void**)&wlp, g_Wlo4);
    cudaGetSymbolAddress((void**)&wfh, g_Wfh4);

    // conversions + exact q row 0
    {
        int n4a = NB * TT * HIDD / 4;
        cvt_a_kernel<<<(n4a + 255) / 256, 256>>>(hs, ahp, alp, afh, afl, n4a);
        int n4w = HIDD * HIDD / 4;
        cvt_w_kernel<<<dim3((n4w + 255) / 256, 3), 256>>>(Wq, Wk, Wv, whp, wlp, wfh, n4w);
        q0_kernel<<<dim3(HIDD, NB), 128>>>(hs, Wq, bq);
    }

    // projections
    {
        size_t ksm = (size_t)(2 * STGW) * sizeof(unsigned);      // 80 KB
        cudaFuncSetAttribute(gemm_k_kernel,
                             cudaFuncAttributeMaxDynamicSharedMemorySize, (int)ksm);
        gemm_k_kernel<<<dim3(HIDD / 128, (NB * TT) / 128), 256, ksm>>>(bk, kp);

        size_t qsm = (size_t)(2 * QV_STGW) * sizeof(unsigned);   // 60 KB
        cudaFuncSetAttribute(gemm_qv_kernel,
                             cudaFuncAttributeMaxDynamicSharedMemorySize, (int)qsm);
        gemm_qv_kernel<<<dim3(HIDD / 128, (NB * TT) / 128, 2), 256, qsm>>>(bq, bv, qp, vp);
    }

    select_kernel<<<dim3(TT / 64, NHH, NB), 64>>>(mask, bq);

    attn_global_kernel<<<dim3(TT / 64, NHH, NB), 64>>>(mask);

    size_t lsmem = (size_t)LSMEM_WORDS * sizeof(float);          // ~98 KB
    cudaFuncSetAttribute(attn_local_tc_kernel,
                         cudaFuncAttributeMaxDynamicSharedMemorySize, (int)lsmem);
    attn_local_tc_kernel<<<dim3(TT / 128, NHH, NB), 256, lsmem>>>(mask, out);

    bos_kernel<<<dim3(NHH, NB), 128>>>(mask, out);
}